// round 12
// baseline (speedup 1.0000x reference)
#include <cuda_runtime.h>
#include <cuda_bf16.h>
#include <cuda_fp16.h>
#include <math.h>
#include <stdint.h>

// Problem constants
#define Bb 4
#define Ts 2048
#define Dd 1024
#define Hh 16
#define HD 64
#define M_ROWS 8192
#define QKV_N 3072

// Scratch (device globals: allocation-free)
__device__ float g_bias[Bb * Ts];                 // per-key log2-domain bias
__device__ int   g_maskMode;
// Fragment-ready fp16 buffers
__device__ uint4 g_qp[(size_t)(M_ROWS / 16) * 64 * 32];   // Q A-pack
__device__ uint4 g_Kq[(size_t)Bb * Hh * 32 * 512];        // K B-pack tiles
__device__ uint4 g_Vq[(size_t)Bb * Hh * 32 * 512];        // V frag tiles
__device__ uint4 g_xp[(size_t)(M_ROWS / 16) * 64 * 32];   // x A-pack
__device__ uint4 g_op[(size_t)(M_ROWS / 16) * 64 * 32];   // attn-out A-pack
__device__ uint4 g_wq[(size_t)(QKV_N / 8) * 32 * 32];     // qkv_w B-pack
__device__ uint4 g_wo[(size_t)(Dd / 8) * 32 * 32];        // out_w B-pack

// ===========================================================================
// helpers
// ===========================================================================
__device__ __forceinline__ uint32_t packf16(float lo, float hi) {
    uint32_t r;
    asm("cvt.rn.f16x2.f32 %0, %1, %2;" : "=r"(r) : "f"(hi), "f"(lo));
    return r;
}
__device__ __forceinline__ float ex2f(float x) {
    float r;
    asm("ex2.approx.ftz.f32 %0, %1;" : "=f"(r) : "f"(x));
    return r;
}

__device__ __forceinline__ void mma_f16(float* c, const uint32_t* a, uint32_t b0, uint32_t b1) {
    asm volatile(
        "mma.sync.aligned.m16n8k16.row.col.f32.f16.f16.f32 "
        "{%0,%1,%2,%3}, {%4,%5,%6,%7}, {%8,%9}, {%0,%1,%2,%3};\n"
        : "+f"(c[0]), "+f"(c[1]), "+f"(c[2]), "+f"(c[3])
        : "r"(a[0]), "r"(a[1]), "r"(a[2]), "r"(a[3]), "r"(b0), "r"(b1));
}
__device__ __forceinline__ void mma_f16q(float* c, const uint4& a, uint32_t b0, uint32_t b1) {
    asm volatile(
        "mma.sync.aligned.m16n8k16.row.col.f32.f16.f16.f32 "
        "{%0,%1,%2,%3}, {%4,%5,%6,%7}, {%8,%9}, {%0,%1,%2,%3};\n"
        : "+f"(c[0]), "+f"(c[1]), "+f"(c[2]), "+f"(c[3])
        : "r"(a.x), "r"(a.y), "r"(a.z), "r"(a.w), "r"(b0), "r"(b1));
}

__device__ __forceinline__ uint32_t smem_u32(const void* p) {
    uint32_t a;
    asm("{ .reg .u64 t; cvta.to.shared.u64 t, %1; cvt.u32.u64 %0, t; }" : "=r"(a) : "l"(p));
    return a;
}
__device__ __forceinline__ void cp_async16(uint32_t dst, const void* src) {
    asm volatile("cp.async.cg.shared.global [%0], [%1], 16;" :: "r"(dst), "l"(src));
}
#define CP_COMMIT() asm volatile("cp.async.commit_group;" ::: "memory")
#define CP_WAIT(n)  asm volatile("cp.async.wait_group %0;" :: "n"(n) : "memory")

// ===========================================================================
// Mask dtype detection + bias precompute (log2 domain)
// ===========================================================================
__global__ void detect_mask_kernel(const unsigned char* __restrict__ mask)
{
    __shared__ unsigned int orr[4][256];
    const int tid = threadIdx.x;
    unsigned int o0 = 0, o1 = 0, o2 = 0, o3 = 0;
    for (int i = tid * 4; i < Bb * Ts; i += 256 * 4) {
        o0 |= mask[i + 0]; o1 |= mask[i + 1]; o2 |= mask[i + 2]; o3 |= mask[i + 3];
    }
    orr[0][tid] = o0; orr[1][tid] = o1; orr[2][tid] = o2; orr[3][tid] = o3;
    __syncthreads();
    for (int s = 128; s; s >>= 1) {
        if (tid < s) {
            orr[0][tid] |= orr[0][tid + s];
            orr[1][tid] |= orr[1][tid + s];
            orr[2][tid] |= orr[2][tid + s];
            orr[3][tid] |= orr[3][tid + s];
        }
        __syncthreads();
    }
    if (tid == 0) {
        unsigned int l0 = orr[0][0], l1 = orr[1][0], l2 = orr[2][0], l3 = orr[3][0];
        int mode;
        if ((l1 | l2 | l3) == 0u) mode = 1;
        else if ((l0 | l1) == 0u && (l2 | l3) != 0u) mode = 2;
        else mode = 0;
        g_maskMode = mode;
    }
}

__global__ void bias_kernel(const float* __restrict__ eng, const void* __restrict__ mask)
{
    const int kk = blockIdx.x * 256 + threadIdx.x;
    if (kk >= Bb * Ts) return;
    const int mode = g_maskMode;
    bool m;
    if (mode == 1)      m = ((const int*)mask)[kk] != 0;
    else if (mode == 2) m = ((const float*)mask)[kk] != 0.f;
    else                m = ((const unsigned char*)mask)[kk] != 0;
    g_bias[kk] = m ? -1e9f : log2f(fmaxf(eng[kk], 1e-6f));
}

// ===========================================================================
// fp16 fragment packing (A- and B-layouts)
// ===========================================================================
__global__ void __launch_bounds__(256)
pack_a_f16(const float* __restrict__ src, uint4* __restrict__ dst, int M, int K)
{
    const int K16 = K >> 4;
    const int total = (M >> 4) * K16 * 32;
    for (int q = blockIdx.x * 256 + threadIdx.x; q < total; q += gridDim.x * 256) {
        const int lane = q & 31;
        const int rs = q >> 5;
        const int S = rs % K16;
        const int R = rs / K16;
        const int g = lane >> 2, t = lane & 3;
        const float* p = src + (size_t)(R * 16 + g) * K + S * 16 + 2 * t;
        const float* p2 = p + (size_t)8 * K;
        const float2 a0 = *(const float2*)(p);
        const float2 a1 = *(const float2*)(p2);
        const float2 a2 = *(const float2*)(p + 8);
        const float2 a3 = *(const float2*)(p2 + 8);
        uint4 w;
        w.x = packf16(a0.x, a0.y);
        w.y = packf16(a1.x, a1.y);
        w.z = packf16(a2.x, a2.y);
        w.w = packf16(a3.x, a3.y);
        dst[q] = w;
    }
}

__global__ void __launch_bounds__(256)
pack_b_f16(const float* __restrict__ src, uint4* __restrict__ dst, int N, int K)
{
    const int K32 = K >> 5;
    const int total = (N >> 3) * K32 * 32;
    for (int q = blockIdx.x * 256 + threadIdx.x; q < total; q += gridDim.x * 256) {
        const int lane = q & 31;
        const int cs = q >> 5;
        const int S = cs % K32;
        const int C = cs / K32;
        const int g = lane >> 2, t = lane & 3;
        const float* p = src + (size_t)(C * 8 + g) * K + S * 32 + 2 * t;
        const float2 b0 = *(const float2*)(p);
        const float2 b1 = *(const float2*)(p + 8);
        const float2 b2 = *(const float2*)(p + 16);
        const float2 b3 = *(const float2*)(p + 24);
        uint4 w;
        w.x = packf16(b0.x, b0.y);
        w.y = packf16(b1.x, b1.y);
        w.z = packf16(b2.x, b2.y);
        w.w = packf16(b3.x, b3.y);
        dst[q] = w;
    }
}

// ===========================================================================
// GEMM: 128x128 tile, BK=32, 4-stage cp.async.
// ===========================================================================
#define GP_SMEM_BYTES 65536

__global__ void __launch_bounds__(256)
f16_gemm_packed(const uint4* __restrict__ Ap, const uint4* __restrict__ Bp,
                const float* __restrict__ bias, float* __restrict__ C,
                int K, int ldc)
{
    extern __shared__ uint4 ps[];
    uint4* sA = ps;
    uint4* sB = ps + 2048;
    const uint32_t sAaddr = smem_u32(sA);
    const uint32_t sBaddr = smem_u32(sB);

    const int tid  = threadIdx.x;
    const int wid  = tid >> 5;
    const int lane = tid & 31;
    const int g = lane >> 2, t = lane & 3;
    const int wm = wid & 3;
    const int wn = wid >> 2;
    const int bm = blockIdx.y * 128;
    const int bn = blockIdx.x * 128;
    const int K16 = K >> 4;
    const int K32 = K >> 5;
    const int Rb = bm >> 4;
    const int Cb = bn >> 3;

    float acc[2][8][4];
#pragma unroll
    for (int mi = 0; mi < 2; ++mi)
#pragma unroll
        for (int ni = 0; ni < 8; ++ni)
#pragma unroll
            for (int r = 0; r < 4; ++r) acc[mi][ni][r] = 0.f;

    auto issue = [&](int buf, int kt) {
#pragma unroll
        for (int i = 0; i < 2; ++i) {
            const int l    = tid + 256 * i;
            const int tile = l >> 5;
            const int ln   = l & 31;
            cp_async16(sAaddr + buf * 8192 + l * 16,
                       Ap + ((size_t)(Rb + (tile >> 1)) * K16 + 2 * kt + (tile & 1)) * 32 + ln);
            cp_async16(sBaddr + buf * 8192 + l * 16,
                       Bp + ((size_t)(Cb + tile) * K32 + kt) * 32 + ln);
        }
    };

    const int nChunks = K >> 5;
#pragma unroll
    for (int p = 0; p < 3; ++p) {
        if (p < nChunks) { issue(p, p); CP_COMMIT(); }
    }

    for (int kt = 0; kt < nChunks; ++kt) {
        if (kt + 3 < nChunks) {
            issue((kt + 3) & 3, kt + 3);
            CP_COMMIT();
            CP_WAIT(3);
        } else if (kt + 2 < nChunks) { CP_WAIT(2); }
        else if (kt + 1 < nChunks)   { CP_WAIT(1); }
        else                         { CP_WAIT(0); }
        __syncthreads();

        const uint4* bufA = sA + (kt & 3) * 512;
        const uint4* bufB = sB + (kt & 3) * 512;
        uint4 fa[2][2];
#pragma unroll
        for (int mi = 0; mi < 2; ++mi)
#pragma unroll
            for (int kc = 0; kc < 2; ++kc)
                fa[mi][kc] = bufA[(((wm * 2 + mi) << 1) | kc) * 32 + lane];
#pragma unroll
        for (int ni = 0; ni < 8; ++ni) {
            const uint4 f = bufB[(wn * 8 + ni) * 32 + lane];
            mma_f16q(acc[0][ni], fa[0][0], f.x, f.y);
            mma_f16q(acc[1][ni], fa[1][0], f.x, f.y);
            mma_f16q(acc[0][ni], fa[0][1], f.z, f.w);
            mma_f16q(acc[1][ni], fa[1][1], f.z, f.w);
        }
        __syncthreads();
    }

#pragma unroll
    for (int mi = 0; mi < 2; ++mi) {
        const int row = bm + wm * 32 + mi * 16 + g;
#pragma unroll
        for (int ni = 0; ni < 8; ++ni) {
            const int col = bn + wn * 64 + ni * 8 + 2 * t;
            const float b0 = bias[col];
            const float b1 = bias[col + 1];
            float2 lo, hi;
            lo.x = acc[mi][ni][0] + b0; lo.y = acc[mi][ni][1] + b1;
            hi.x = acc[mi][ni][2] + b0; hi.y = acc[mi][ni][3] + b1;
            *(float2*)(C + (size_t)row * ldc + col) = lo;
            *(float2*)(C + (size_t)(row + 8) * ldc + col) = hi;
        }
    }
}

// ===========================================================================
// Fused QKV GEMM (unchanged from round 11)
// ===========================================================================
__global__ void __launch_bounds__(256)
qkv_gemm_fused(const uint4* __restrict__ Ap, const uint4* __restrict__ Bp,
               const float* __restrict__ bias,
               uint4* __restrict__ Qp, uint4* __restrict__ Kq, uint4* __restrict__ Vq)
{
    extern __shared__ uint4 ps[];
    uint4* sA = ps;
    uint4* sB = ps + 2048;
    const uint32_t sAaddr = smem_u32(sA);
    const uint32_t sBaddr = smem_u32(sB);

    const int tid  = threadIdx.x;
    const int wid  = tid >> 5;
    const int lane = tid & 31;
    const int g = lane >> 2, t = lane & 3;
    const int wm = wid & 3;
    const int wn = wid >> 2;
    const int bm = blockIdx.y * 128;
    const int bn = blockIdx.x * 128;
    const int K16 = Dd >> 4;
    const int K32 = Dd >> 5;
    const int Rb = bm >> 4;
    const int Cb = bn >> 3;

    float acc[2][8][4];
#pragma unroll
    for (int mi = 0; mi < 2; ++mi)
#pragma unroll
        for (int ni = 0; ni < 8; ++ni)
#pragma unroll
            for (int r = 0; r < 4; ++r) acc[mi][ni][r] = 0.f;

    auto issue = [&](int buf, int kt) {
#pragma unroll
        for (int i = 0; i < 2; ++i) {
            const int l    = tid + 256 * i;
            const int tile = l >> 5;
            const int ln   = l & 31;
            cp_async16(sAaddr + buf * 8192 + l * 16,
                       Ap + ((size_t)(Rb + (tile >> 1)) * K16 + 2 * kt + (tile & 1)) * 32 + ln);
            cp_async16(sBaddr + buf * 8192 + l * 16,
                       Bp + ((size_t)(Cb + tile) * K32 + kt) * 32 + ln);
        }
    };

    const int nChunks = Dd >> 5;
#pragma unroll
    for (int p = 0; p < 3; ++p) { issue(p, p); CP_COMMIT(); }

    for (int kt = 0; kt < nChunks; ++kt) {
        if (kt + 3 < nChunks) {
            issue((kt + 3) & 3, kt + 3);
            CP_COMMIT();
            CP_WAIT(3);
        } else if (kt + 2 < nChunks) { CP_WAIT(2); }
        else if (kt + 1 < nChunks)   { CP_WAIT(1); }
        else                         { CP_WAIT(0); }
        __syncthreads();

        const uint4* bufA = sA + (kt & 3) * 512;
        const uint4* bufB = sB + (kt & 3) * 512;
        uint4 fa[2][2];
#pragma unroll
        for (int mi = 0; mi < 2; ++mi)
#pragma unroll
            for (int kc = 0; kc < 2; ++kc)
                fa[mi][kc] = bufA[(((wm * 2 + mi) << 1) | kc) * 32 + lane];
#pragma unroll
        for (int ni = 0; ni < 8; ++ni) {
            const uint4 f = bufB[(wn * 8 + ni) * 32 + lane];
            mma_f16q(acc[0][ni], fa[0][0], f.x, f.y);
            mma_f16q(acc[1][ni], fa[1][0], f.x, f.y);
            mma_f16q(acc[0][ni], fa[0][1], f.z, f.w);
            mma_f16q(acc[1][ni], fa[1][1], f.z, f.w);
        }
        __syncthreads();
    }

    const int region = blockIdx.x >> 3;

    if (region == 0) {
#pragma unroll
        for (int mi = 0; mi < 2; ++mi) {
            const int R = Rb + wm * 2 + mi;
#pragma unroll
            for (int s = 0; s < 4; ++s) {
                const int colb = bn + wn * 64 + s * 16;
                const float b0 = bias[colb + 2 * t];
                const float b1 = bias[colb + 2 * t + 1];
                const float b2 = bias[colb + 8 + 2 * t];
                const float b3 = bias[colb + 8 + 2 * t + 1];
                uint4 w;
                w.x = packf16(acc[mi][2 * s][0] + b0,     acc[mi][2 * s][1] + b1);
                w.y = packf16(acc[mi][2 * s][2] + b0,     acc[mi][2 * s][3] + b1);
                w.z = packf16(acc[mi][2 * s + 1][0] + b2, acc[mi][2 * s + 1][1] + b3);
                w.w = packf16(acc[mi][2 * s + 1][2] + b2, acc[mi][2 * s + 1][3] + b3);
                const int Scol = blockIdx.x * 8 + wn * 4 + s;
                Qp[((size_t)R * 64 + Scol) * 32 + lane] = w;
            }
        }
    } else if (region == 1) {
        const int h = (blockIdx.x - 8) * 2 + wn;
#pragma unroll
        for (int mi = 0; mi < 2; ++mi) {
            const int rowbase = bm + wm * 32 + mi * 16;
            const int bb  = rowbase >> 11;
            const int tok = rowbase & 2047;
            const int kt  = tok >> 6;
            const int nt0 = (tok >> 3) & 7;
            const size_t base = ((size_t)(bb * Hh + h) * 32 + kt) * 512;
#pragma unroll
            for (int ksp = 0; ksp < 2; ++ksp) {
                const int colb = bn + wn * 64 + 32 * ksp;
                float bb0[4], bb1[4];
#pragma unroll
                for (int j = 0; j < 4; ++j) {
                    bb0[j] = bias[colb + 8 * j + 2 * t];
                    bb1[j] = bias[colb + 8 * j + 2 * t + 1];
                }
                uint4 w0, w1;
                w0.x = packf16(acc[mi][4 * ksp + 0][0] + bb0[0], acc[mi][4 * ksp + 0][1] + bb1[0]);
                w0.y = packf16(acc[mi][4 * ksp + 1][0] + bb0[1], acc[mi][4 * ksp + 1][1] + bb1[1]);
                w0.z = packf16(acc[mi][4 * ksp + 2][0] + bb0[2], acc[mi][4 * ksp + 2][1] + bb1[2]);
                w0.w = packf16(acc[mi][4 * ksp + 3][0] + bb0[3], acc[mi][4 * ksp + 3][1] + bb1[3]);
                w1.x = packf16(acc[mi][4 * ksp + 0][2] + bb0[0], acc[mi][4 * ksp + 0][3] + bb1[0]);
                w1.y = packf16(acc[mi][4 * ksp + 1][2] + bb0[1], acc[mi][4 * ksp + 1][3] + bb1[1]);
                w1.z = packf16(acc[mi][4 * ksp + 2][2] + bb0[2], acc[mi][4 * ksp + 2][3] + bb1[2]);
                w1.w = packf16(acc[mi][4 * ksp + 3][2] + bb0[3], acc[mi][4 * ksp + 3][3] + bb1[3]);
                Kq[base + ((size_t)(nt0 * 2 + ksp)) * 32 + lane] = w0;
                Kq[base + ((size_t)((nt0 + 1) * 2 + ksp)) * 32 + lane] = w1;
            }
        }
    } else {
        unsigned short* sT = (unsigned short*)ps;
#pragma unroll
        for (int mi = 0; mi < 2; ++mi) {
            const int r0 = wm * 32 + mi * 16 + g;
#pragma unroll
            for (int ni = 0; ni < 8; ++ni) {
                const int c = wn * 64 + ni * 8 + 2 * t;
                const float b0 = bias[bn + c];
                const float b1 = bias[bn + c + 1];
                *(uint32_t*)&sT[r0 * 136 + c]       = packf16(acc[mi][ni][0] + b0, acc[mi][ni][1] + b1);
                *(uint32_t*)&sT[(r0 + 8) * 136 + c] = packf16(acc[mi][ni][2] + b0, acc[mi][ni][3] + b1);
            }
        }
        __syncthreads();

        const int bb   = bm >> 11;
        const int tokb = bm & 2047;
#pragma unroll
        for (int i = 0; i < 8; ++i) {
            const int q6   = i * 8 + (tid >> 5);
            const int head = q6 >> 5;
            const int kt2  = (q6 >> 4) & 1;
            const int kp   = (q6 >> 2) & 3;
            const int nd2  = q6 & 3;
            const int r0 = kt2 * 64 + kp * 16 + 2 * t;
            const int c0 = head * 64 + nd2 * 16 + g;
            uint4 w;
            w.x = (uint32_t)sT[r0 * 136 + c0]           | ((uint32_t)sT[(r0 + 1) * 136 + c0] << 16);
            w.y = (uint32_t)sT[(r0 + 8) * 136 + c0]     | ((uint32_t)sT[(r0 + 9) * 136 + c0] << 16);
            w.z = (uint32_t)sT[r0 * 136 + c0 + 8]       | ((uint32_t)sT[(r0 + 1) * 136 + c0 + 8] << 16);
            w.w = (uint32_t)sT[(r0 + 8) * 136 + c0 + 8] | ((uint32_t)sT[(r0 + 9) * 136 + c0 + 8] << 16);
            const int hg  = (blockIdx.x - 16) * 2 + head;
            const int ktg = (tokb >> 6) + kt2;
            Vq[((size_t)(bb * Hh + hg) * 32 + ktg) * 512 + (kp * 4 + nd2) * 32 + lane] = w;
        }
    }
}

// ===========================================================================
// Flash attention: 256 threads / 128 queries per CTA, 3-stage cp.async,
// all-fp16 MMA, no-max ex2 softmax, fused fp16 A-pack epilogue.
// ===========================================================================
#define ATTN_SMEM_BYTES (3 * 8192 + 3 * 8192 + 3 * 256)
#define C1 0.18033688011112042f   // 0.125 * log2(e)

__global__ void __launch_bounds__(256, 2)
attn_kernel(const uint4* __restrict__ Qp, uint4* __restrict__ Opacked)
{
    extern __shared__ uint4 asm4[];
    uint4* sK = asm4;                      // [3][512]
    uint4* sV = asm4 + 3 * 512;            // [3][512]
    float* sBias = (float*)(asm4 + 6 * 512);  // [3][64]

    const uint32_t sKaddr = smem_u32(sK);
    const uint32_t sVaddr = smem_u32(sV);
    const uint32_t sBaddr = smem_u32(sBias);

    const int qt = blockIdx.x;     // 128-query tile
    const int h  = blockIdx.y;
    const int b  = blockIdx.z;
    const int tid  = threadIdx.x;
    const int warp = tid >> 5;     // 0..7
    const int lane = tid & 31;
    const int t = lane & 3;

    const size_t kvBase = ((size_t)(b * Hh + h)) * 32 * 512;
    const int R = (b * Ts + qt * 128 + warp * 16) >> 4;

    // Q fragments straight from the A-pack
    uint4 qf[4];
#pragma unroll
    for (int ks = 0; ks < 4; ++ks)
        qf[ks] = Qp[((size_t)R * 64 + h * 4 + ks) * 32 + lane];

    float o[8][4];
#pragma unroll
    for (int i = 0; i < 8; ++i)
#pragma unroll
        for (int j = 0; j < 4; ++j) o[i][j] = 0.f;
    float l0 = 0.f, l1 = 0.f;

    // 256 threads: 2 cp.async K + 2 V per thread per tile
    auto issue = [&](int buf, int kt) {
        const uint4* srcK = g_Kq + kvBase + (size_t)kt * 512 + tid;
        const uint4* srcV = g_Vq + kvBase + (size_t)kt * 512 + tid;
        const uint32_t dK = sKaddr + buf * 8192 + tid * 16;
        const uint32_t dV = sVaddr + buf * 8192 + tid * 16;
#pragma unroll
        for (int i = 0; i < 2; ++i) {
            cp_async16(dK + i * 4096, srcK + i * 256);
            cp_async16(dV + i * 4096, srcV + i * 256);
        }
        if (tid < 16) cp_async16(sBaddr + buf * 256 + tid * 16, g_bias + b * Ts + kt * 64 + tid * 4);
    };

    issue(0, 0); CP_COMMIT();
    issue(1, 1); CP_COMMIT();

    const int nT = Ts / 64;
    int buf = 0;
    for (int kt = 0; kt < nT; ++kt) {
        if (kt + 2 < nT) {
            issue((kt + 2) % 3, kt + 2);
            CP_COMMIT();
            CP_WAIT(2);
        } else if (kt + 1 < nT) { CP_WAIT(1); }
        else                    { CP_WAIT(0); }
        __syncthreads();

        const uint4* bK = sK + buf * 512;
        const uint4* bV = sV + buf * 512;
        const float* bB = sBias + buf * 64;

        // ---- S = Q K^T (fp16) ----
        float sacc[8][4];
#pragma unroll
        for (int nt = 0; nt < 8; ++nt)
#pragma unroll
            for (int j = 0; j < 4; ++j) sacc[nt][j] = 0.f;
#pragma unroll
        for (int ksp = 0; ksp < 2; ++ksp) {
#pragma unroll
            for (int nt = 0; nt < 8; ++nt) {
                const uint4 f = bK[(nt * 2 + ksp) * 32 + lane];
                mma_f16q(sacc[nt], qf[2 * ksp], f.x, f.y);
                mma_f16q(sacc[nt], qf[2 * ksp + 1], f.z, f.w);
            }
        }

        // ---- softmax weights (no max): P = exp2(S*C1 + log2bias) ----
        float rs0 = 0.f, rs1 = 0.f;
        uint32_t ph[8][2];
#pragma unroll
        for (int nt = 0; nt < 8; ++nt) {
            const float2 bb2 = *(const float2*)(bB + 8 * nt + 2 * t);
            const float p0 = ex2f(fmaf(sacc[nt][0], C1, bb2.x));
            const float p1 = ex2f(fmaf(sacc[nt][1], C1, bb2.y));
            const float p2 = ex2f(fmaf(sacc[nt][2], C1, bb2.x));
            const float p3 = ex2f(fmaf(sacc[nt][3], C1, bb2.y));
            rs0 += p0 + p1;
            rs1 += p2 + p3;
            ph[nt][0] = packf16(p0, p1);
            ph[nt][1] = packf16(p2, p3);
        }
        l0 += rs0;
        l1 += rs1;

        // ---- O += P V (fp16) ----
#pragma unroll
        for (int kp = 0; kp < 4; ++kp) {
            const uint32_t a[4] = { ph[2 * kp][0], ph[2 * kp][1],
                                    ph[2 * kp + 1][0], ph[2 * kp + 1][1] };
#pragma unroll
            for (int nd2 = 0; nd2 < 4; ++nd2) {
                const uint4 f = bV[(kp * 4 + nd2) * 32 + lane];
                mma_f16(o[2 * nd2], a, f.x, f.y);
                mma_f16(o[2 * nd2 + 1], a, f.z, f.w);
            }
        }
        __syncthreads();
        buf = (buf + 1) % 3;
    }

    // row sums across 4 t-lanes
    l0 += __shfl_xor_sync(0xffffffffu, l0, 1);
    l0 += __shfl_xor_sync(0xffffffffu, l0, 2);
    l1 += __shfl_xor_sync(0xffffffffu, l1, 1);
    l1 += __shfl_xor_sync(0xffffffffu, l1, 2);
    const float inv0 = 1.0f / l0;
    const float inv1 = 1.0f / l1;

    // fused epilogue: normalize + write fp16 A-pack quads
#pragma unroll
    for (int sd = 0; sd < 4; ++sd) {
        uint4 w;
        w.x = packf16(o[2 * sd][0] * inv0,     o[2 * sd][1] * inv0);
        w.y = packf16(o[2 * sd][2] * inv1,     o[2 * sd][3] * inv1);
        w.z = packf16(o[2 * sd + 1][0] * inv0, o[2 * sd + 1][1] * inv0);
        w.w = packf16(o[2 * sd + 1][2] * inv1, o[2 * sd + 1][3] * inv1);
        Opacked[((size_t)R * 64 + h * 4 + sd) * 32 + lane] = w;
    }
}

// ===========================================================================
extern "C" void kernel_launch(void* const* d_in, const int* in_sizes, int n_in,
                              void* d_out, int out_size)
{
    const float* x     = (const float*)d_in[0];
    const float* eng   = (const float*)d_in[1];
    const void*  mask  = (const void*)d_in[2];
    const float* qkv_w = (const float*)d_in[3];
    const float* qkv_b = (const float*)d_in[4];
    const float* out_w = (const float*)d_in[5];
    const float* out_b = (const float*)d_in[6];
    float* out = (float*)d_out;

    uint4 *qp = nullptr, *kq = nullptr, *vq = nullptr;
    uint4 *xp = nullptr, *op = nullptr, *wq = nullptr, *wo = nullptr;
    cudaGetSymbolAddress((void**)&qp, g_qp);
    cudaGetSymbolAddress((void**)&kq, g_Kq);
    cudaGetSymbolAddress((void**)&vq, g_Vq);
    cudaGetSymbolAddress((void**)&xp, g_xp);
    cudaGetSymbolAddress((void**)&op, g_op);
    cudaGetSymbolAddress((void**)&wq, g_wq);
    cudaGetSymbolAddress((void**)&wo, g_wo);

    cudaFuncSetAttribute(f16_gemm_packed,
                         cudaFuncAttributeMaxDynamicSharedMemorySize, GP_SMEM_BYTES);
    cudaFuncSetAttribute(qkv_gemm_fused,
                         cudaFuncAttributeMaxDynamicSharedMemorySize, GP_SMEM_BYTES);
    cudaFuncSetAttribute(attn_kernel,
                         cudaFuncAttributeMaxDynamicSharedMemorySize, ATTN_SMEM_BYTES);

    // 0) mask dtype detection + per-key bias precompute (log2 domain)
    detect_mask_kernel<<<1, 256>>>((const unsigned char*)mask);
    bias_kernel<<<(Bb * Ts + 255) / 256, 256>>>(eng, mask);

    // 0b) pack x and weights into fp16 fragment layouts
    pack_a_f16<<<2048, 256>>>(x, xp, M_ROWS, Dd);
    pack_b_f16<<<1536, 256>>>(qkv_w, wq, QKV_N, Dd);
    pack_b_f16<<<512, 256>>>(out_w, wo, Dd, Dd);

    // 1) fused QKV projection -> Q A-pack, K B-pack, V frag tiles
    dim3 g1(QKV_N / 128, M_ROWS / 128);
    qkv_gemm_fused<<<g1, 256, GP_SMEM_BYTES>>>(xp, wq, qkv_b, qp, kq, vq);

    // 2) attention (all-fp16 MMA, 128 queries/CTA) -> fp16 A-pack
    dim3 g2(Ts / 128, Hh, Bb);
    attn_kernel<<<g2, 256, ATTN_SMEM_BYTES>>>(qp, op);

    // 3) output projection (packed fp16 mma.sync, 4-stage pipeline)
    dim3 g3(Dd / 128, M_ROWS / 128);
    f16_gemm_packed<<<g3, 256, GP_SMEM_BYTES>>>(op, wo, out_b, out, Dd, Dd);
}

// round 13
// speedup vs baseline: 1.0041x; 1.0041x over previous
#include <cuda_runtime.h>
#include <cuda_bf16.h>
#include <cuda_fp16.h>
#include <math.h>
#include <stdint.h>

// Problem constants
#define Bb 4
#define Ts 2048
#define Dd 1024
#define Hh 16
#define HD 64
#define M_ROWS 8192
#define QKV_N 3072

// Scratch (device globals: allocation-free)
__device__ float g_bias[Bb * Ts];                 // per-key log2-domain bias
__device__ int   g_maskMode;
// Fragment-ready fp16 buffers
__device__ uint4 g_qp[(size_t)(M_ROWS / 16) * 64 * 32];   // Q A-pack
__device__ uint4 g_Kq[(size_t)Bb * Hh * 32 * 512];        // K B-pack tiles
__device__ uint4 g_Vq[(size_t)Bb * Hh * 32 * 512];        // V frag tiles
__device__ uint4 g_xp[(size_t)(M_ROWS / 16) * 64 * 32];   // x A-pack
__device__ uint4 g_op[(size_t)(M_ROWS / 16) * 64 * 32];   // attn-out A-pack
__device__ uint4 g_wq[(size_t)(QKV_N / 8) * 32 * 32];     // qkv_w B-pack
__device__ uint4 g_wo[(size_t)(Dd / 8) * 32 * 32];        // out_w B-pack

// ===========================================================================
// helpers
// ===========================================================================
__device__ __forceinline__ uint32_t packf16(float lo, float hi) {
    uint32_t r;
    asm("cvt.rn.f16x2.f32 %0, %1, %2;" : "=r"(r) : "f"(hi), "f"(lo));
    return r;
}
__device__ __forceinline__ uint32_t ex2_f16x2(uint32_t x) {
    uint32_t r;
    asm("ex2.approx.f16x2 %0, %1;" : "=r"(r) : "r"(x));
    return r;
}

__device__ __forceinline__ void mma_f16(float* c, const uint32_t* a, uint32_t b0, uint32_t b1) {
    asm volatile(
        "mma.sync.aligned.m16n8k16.row.col.f32.f16.f16.f32 "
        "{%0,%1,%2,%3}, {%4,%5,%6,%7}, {%8,%9}, {%0,%1,%2,%3};\n"
        : "+f"(c[0]), "+f"(c[1]), "+f"(c[2]), "+f"(c[3])
        : "r"(a[0]), "r"(a[1]), "r"(a[2]), "r"(a[3]), "r"(b0), "r"(b1));
}
__device__ __forceinline__ void mma_f16q(float* c, const uint4& a, uint32_t b0, uint32_t b1) {
    asm volatile(
        "mma.sync.aligned.m16n8k16.row.col.f32.f16.f16.f32 "
        "{%0,%1,%2,%3}, {%4,%5,%6,%7}, {%8,%9}, {%0,%1,%2,%3};\n"
        : "+f"(c[0]), "+f"(c[1]), "+f"(c[2]), "+f"(c[3])
        : "r"(a.x), "r"(a.y), "r"(a.z), "r"(a.w), "r"(b0), "r"(b1));
}

__device__ __forceinline__ uint32_t smem_u32(const void* p) {
    uint32_t a;
    asm("{ .reg .u64 t; cvta.to.shared.u64 t, %1; cvt.u32.u64 %0, t; }" : "=r"(a) : "l"(p));
    return a;
}
__device__ __forceinline__ void cp_async16(uint32_t dst, const void* src) {
    asm volatile("cp.async.cg.shared.global [%0], [%1], 16;" :: "r"(dst), "l"(src));
}
#define CP_COMMIT() asm volatile("cp.async.commit_group;" ::: "memory")
#define CP_WAIT(n)  asm volatile("cp.async.wait_group %0;" :: "n"(n) : "memory")

// ===========================================================================
// Mask dtype detection + bias precompute (log2 domain)
// ===========================================================================
__global__ void detect_mask_kernel(const unsigned char* __restrict__ mask)
{
    __shared__ unsigned int orr[4][256];
    const int tid = threadIdx.x;
    unsigned int o0 = 0, o1 = 0, o2 = 0, o3 = 0;
    for (int i = tid * 4; i < Bb * Ts; i += 256 * 4) {
        o0 |= mask[i + 0]; o1 |= mask[i + 1]; o2 |= mask[i + 2]; o3 |= mask[i + 3];
    }
    orr[0][tid] = o0; orr[1][tid] = o1; orr[2][tid] = o2; orr[3][tid] = o3;
    __syncthreads();
    for (int s = 128; s; s >>= 1) {
        if (tid < s) {
            orr[0][tid] |= orr[0][tid + s];
            orr[1][tid] |= orr[1][tid + s];
            orr[2][tid] |= orr[2][tid + s];
            orr[3][tid] |= orr[3][tid + s];
        }
        __syncthreads();
    }
    if (tid == 0) {
        unsigned int l0 = orr[0][0], l1 = orr[1][0], l2 = orr[2][0], l3 = orr[3][0];
        int mode;
        if ((l1 | l2 | l3) == 0u) mode = 1;
        else if ((l0 | l1) == 0u && (l2 | l3) != 0u) mode = 2;
        else mode = 0;
        g_maskMode = mode;
    }
}

__global__ void bias_kernel(const float* __restrict__ eng, const void* __restrict__ mask)
{
    const int kk = blockIdx.x * 256 + threadIdx.x;
    if (kk >= Bb * Ts) return;
    const int mode = g_maskMode;
    bool m;
    if (mode == 1)      m = ((const int*)mask)[kk] != 0;
    else if (mode == 2) m = ((const float*)mask)[kk] != 0.f;
    else                m = ((const unsigned char*)mask)[kk] != 0;
    g_bias[kk] = m ? -1e9f : log2f(fmaxf(eng[kk], 1e-6f));
}

// ===========================================================================
// fp16 fragment packing (A- and B-layouts)
// ===========================================================================
__global__ void __launch_bounds__(256)
pack_a_f16(const float* __restrict__ src, uint4* __restrict__ dst, int M, int K)
{
    const int K16 = K >> 4;
    const int total = (M >> 4) * K16 * 32;
    for (int q = blockIdx.x * 256 + threadIdx.x; q < total; q += gridDim.x * 256) {
        const int lane = q & 31;
        const int rs = q >> 5;
        const int S = rs % K16;
        const int R = rs / K16;
        const int g = lane >> 2, t = lane & 3;
        const float* p = src + (size_t)(R * 16 + g) * K + S * 16 + 2 * t;
        const float* p2 = p + (size_t)8 * K;
        const float2 a0 = *(const float2*)(p);
        const float2 a1 = *(const float2*)(p2);
        const float2 a2 = *(const float2*)(p + 8);
        const float2 a3 = *(const float2*)(p2 + 8);
        uint4 w;
        w.x = packf16(a0.x, a0.y);
        w.y = packf16(a1.x, a1.y);
        w.z = packf16(a2.x, a2.y);
        w.w = packf16(a3.x, a3.y);
        dst[q] = w;
    }
}

__global__ void __launch_bounds__(256)
pack_b_f16(const float* __restrict__ src, uint4* __restrict__ dst, int N, int K)
{
    const int K32 = K >> 5;
    const int total = (N >> 3) * K32 * 32;
    for (int q = blockIdx.x * 256 + threadIdx.x; q < total; q += gridDim.x * 256) {
        const int lane = q & 31;
        const int cs = q >> 5;
        const int S = cs % K32;
        const int C = cs / K32;
        const int g = lane >> 2, t = lane & 3;
        const float* p = src + (size_t)(C * 8 + g) * K + S * 32 + 2 * t;
        const float2 b0 = *(const float2*)(p);
        const float2 b1 = *(const float2*)(p + 8);
        const float2 b2 = *(const float2*)(p + 16);
        const float2 b3 = *(const float2*)(p + 24);
        uint4 w;
        w.x = packf16(b0.x, b0.y);
        w.y = packf16(b1.x, b1.y);
        w.z = packf16(b2.x, b2.y);
        w.w = packf16(b3.x, b3.y);
        dst[q] = w;
    }
}

// ===========================================================================
// GEMM: 128x128 tile, BK=32, 4-stage cp.async.
// ===========================================================================
#define GP_SMEM_BYTES 65536

__global__ void __launch_bounds__(256)
f16_gemm_packed(const uint4* __restrict__ Ap, const uint4* __restrict__ Bp,
                const float* __restrict__ bias, float* __restrict__ C,
                int K, int ldc)
{
    extern __shared__ uint4 ps[];
    uint4* sA = ps;
    uint4* sB = ps + 2048;
    const uint32_t sAaddr = smem_u32(sA);
    const uint32_t sBaddr = smem_u32(sB);

    const int tid  = threadIdx.x;
    const int wid  = tid >> 5;
    const int lane = tid & 31;
    const int g = lane >> 2, t = lane & 3;
    const int wm = wid & 3;
    const int wn = wid >> 2;
    const int bm = blockIdx.y * 128;
    const int bn = blockIdx.x * 128;
    const int K16 = K >> 4;
    const int K32 = K >> 5;
    const int Rb = bm >> 4;
    const int Cb = bn >> 3;

    float acc[2][8][4];
#pragma unroll
    for (int mi = 0; mi < 2; ++mi)
#pragma unroll
        for (int ni = 0; ni < 8; ++ni)
#pragma unroll
            for (int r = 0; r < 4; ++r) acc[mi][ni][r] = 0.f;

    auto issue = [&](int buf, int kt) {
#pragma unroll
        for (int i = 0; i < 2; ++i) {
            const int l    = tid + 256 * i;
            const int tile = l >> 5;
            const int ln   = l & 31;
            cp_async16(sAaddr + buf * 8192 + l * 16,
                       Ap + ((size_t)(Rb + (tile >> 1)) * K16 + 2 * kt + (tile & 1)) * 32 + ln);
            cp_async16(sBaddr + buf * 8192 + l * 16,
                       Bp + ((size_t)(Cb + tile) * K32 + kt) * 32 + ln);
        }
    };

    const int nChunks = K >> 5;
#pragma unroll
    for (int p = 0; p < 3; ++p) {
        if (p < nChunks) { issue(p, p); CP_COMMIT(); }
    }

    for (int kt = 0; kt < nChunks; ++kt) {
        if (kt + 3 < nChunks) {
            issue((kt + 3) & 3, kt + 3);
            CP_COMMIT();
            CP_WAIT(3);
        } else if (kt + 2 < nChunks) { CP_WAIT(2); }
        else if (kt + 1 < nChunks)   { CP_WAIT(1); }
        else                         { CP_WAIT(0); }
        __syncthreads();

        const uint4* bufA = sA + (kt & 3) * 512;
        const uint4* bufB = sB + (kt & 3) * 512;
        uint4 fa[2][2];
#pragma unroll
        for (int mi = 0; mi < 2; ++mi)
#pragma unroll
            for (int kc = 0; kc < 2; ++kc)
                fa[mi][kc] = bufA[(((wm * 2 + mi) << 1) | kc) * 32 + lane];
#pragma unroll
        for (int ni = 0; ni < 8; ++ni) {
            const uint4 f = bufB[(wn * 8 + ni) * 32 + lane];
            mma_f16q(acc[0][ni], fa[0][0], f.x, f.y);
            mma_f16q(acc[1][ni], fa[1][0], f.x, f.y);
            mma_f16q(acc[0][ni], fa[0][1], f.z, f.w);
            mma_f16q(acc[1][ni], fa[1][1], f.z, f.w);
        }
        __syncthreads();
    }

#pragma unroll
    for (int mi = 0; mi < 2; ++mi) {
        const int row = bm + wm * 32 + mi * 16 + g;
#pragma unroll
        for (int ni = 0; ni < 8; ++ni) {
            const int col = bn + wn * 64 + ni * 8 + 2 * t;
            const float b0 = bias[col];
            const float b1 = bias[col + 1];
            float2 lo, hi;
            lo.x = acc[mi][ni][0] + b0; lo.y = acc[mi][ni][1] + b1;
            hi.x = acc[mi][ni][2] + b0; hi.y = acc[mi][ni][3] + b1;
            *(float2*)(C + (size_t)row * ldc + col) = lo;
            *(float2*)(C + (size_t)(row + 8) * ldc + col) = hi;
        }
    }
}

// ===========================================================================
// Fused QKV GEMM (unchanged from round 11)
// ===========================================================================
__global__ void __launch_bounds__(256)
qkv_gemm_fused(const uint4* __restrict__ Ap, const uint4* __restrict__ Bp,
               const float* __restrict__ bias,
               uint4* __restrict__ Qp, uint4* __restrict__ Kq, uint4* __restrict__ Vq)
{
    extern __shared__ uint4 ps[];
    uint4* sA = ps;
    uint4* sB = ps + 2048;
    const uint32_t sAaddr = smem_u32(sA);
    const uint32_t sBaddr = smem_u32(sB);

    const int tid  = threadIdx.x;
    const int wid  = tid >> 5;
    const int lane = tid & 31;
    const int g = lane >> 2, t = lane & 3;
    const int wm = wid & 3;
    const int wn = wid >> 2;
    const int bm = blockIdx.y * 128;
    const int bn = blockIdx.x * 128;
    const int K16 = Dd >> 4;
    const int K32 = Dd >> 5;
    const int Rb = bm >> 4;
    const int Cb = bn >> 3;

    float acc[2][8][4];
#pragma unroll
    for (int mi = 0; mi < 2; ++mi)
#pragma unroll
        for (int ni = 0; ni < 8; ++ni)
#pragma unroll
            for (int r = 0; r < 4; ++r) acc[mi][ni][r] = 0.f;

    auto issue = [&](int buf, int kt) {
#pragma unroll
        for (int i = 0; i < 2; ++i) {
            const int l    = tid + 256 * i;
            const int tile = l >> 5;
            const int ln   = l & 31;
            cp_async16(sAaddr + buf * 8192 + l * 16,
                       Ap + ((size_t)(Rb + (tile >> 1)) * K16 + 2 * kt + (tile & 1)) * 32 + ln);
            cp_async16(sBaddr + buf * 8192 + l * 16,
                       Bp + ((size_t)(Cb + tile) * K32 + kt) * 32 + ln);
        }
    };

    const int nChunks = Dd >> 5;
#pragma unroll
    for (int p = 0; p < 3; ++p) { issue(p, p); CP_COMMIT(); }

    for (int kt = 0; kt < nChunks; ++kt) {
        if (kt + 3 < nChunks) {
            issue((kt + 3) & 3, kt + 3);
            CP_COMMIT();
            CP_WAIT(3);
        } else if (kt + 2 < nChunks) { CP_WAIT(2); }
        else if (kt + 1 < nChunks)   { CP_WAIT(1); }
        else                         { CP_WAIT(0); }
        __syncthreads();

        const uint4* bufA = sA + (kt & 3) * 512;
        const uint4* bufB = sB + (kt & 3) * 512;
        uint4 fa[2][2];
#pragma unroll
        for (int mi = 0; mi < 2; ++mi)
#pragma unroll
            for (int kc = 0; kc < 2; ++kc)
                fa[mi][kc] = bufA[(((wm * 2 + mi) << 1) | kc) * 32 + lane];
#pragma unroll
        for (int ni = 0; ni < 8; ++ni) {
            const uint4 f = bufB[(wn * 8 + ni) * 32 + lane];
            mma_f16q(acc[0][ni], fa[0][0], f.x, f.y);
            mma_f16q(acc[1][ni], fa[1][0], f.x, f.y);
            mma_f16q(acc[0][ni], fa[0][1], f.z, f.w);
            mma_f16q(acc[1][ni], fa[1][1], f.z, f.w);
        }
        __syncthreads();
    }

    const int region = blockIdx.x >> 3;

    if (region == 0) {
#pragma unroll
        for (int mi = 0; mi < 2; ++mi) {
            const int R = Rb + wm * 2 + mi;
#pragma unroll
            for (int s = 0; s < 4; ++s) {
                const int colb = bn + wn * 64 + s * 16;
                const float b0 = bias[colb + 2 * t];
                const float b1 = bias[colb + 2 * t + 1];
                const float b2 = bias[colb + 8 + 2 * t];
                const float b3 = bias[colb + 8 + 2 * t + 1];
                uint4 w;
                w.x = packf16(acc[mi][2 * s][0] + b0,     acc[mi][2 * s][1] + b1);
                w.y = packf16(acc[mi][2 * s][2] + b0,     acc[mi][2 * s][3] + b1);
                w.z = packf16(acc[mi][2 * s + 1][0] + b2, acc[mi][2 * s + 1][1] + b3);
                w.w = packf16(acc[mi][2 * s + 1][2] + b2, acc[mi][2 * s + 1][3] + b3);
                const int Scol = blockIdx.x * 8 + wn * 4 + s;
                Qp[((size_t)R * 64 + Scol) * 32 + lane] = w;
            }
        }
    } else if (region == 1) {
        const int h = (blockIdx.x - 8) * 2 + wn;
#pragma unroll
        for (int mi = 0; mi < 2; ++mi) {
            const int rowbase = bm + wm * 32 + mi * 16;
            const int bb  = rowbase >> 11;
            const int tok = rowbase & 2047;
            const int kt  = tok >> 6;
            const int nt0 = (tok >> 3) & 7;
            const size_t base = ((size_t)(bb * Hh + h) * 32 + kt) * 512;
#pragma unroll
            for (int ksp = 0; ksp < 2; ++ksp) {
                const int colb = bn + wn * 64 + 32 * ksp;
                float bb0[4], bb1[4];
#pragma unroll
                for (int j = 0; j < 4; ++j) {
                    bb0[j] = bias[colb + 8 * j + 2 * t];
                    bb1[j] = bias[colb + 8 * j + 2 * t + 1];
                }
                uint4 w0, w1;
                w0.x = packf16(acc[mi][4 * ksp + 0][0] + bb0[0], acc[mi][4 * ksp + 0][1] + bb1[0]);
                w0.y = packf16(acc[mi][4 * ksp + 1][0] + bb0[1], acc[mi][4 * ksp + 1][1] + bb1[1]);
                w0.z = packf16(acc[mi][4 * ksp + 2][0] + bb0[2], acc[mi][4 * ksp + 2][1] + bb1[2]);
                w0.w = packf16(acc[mi][4 * ksp + 3][0] + bb0[3], acc[mi][4 * ksp + 3][1] + bb1[3]);
                w1.x = packf16(acc[mi][4 * ksp + 0][2] + bb0[0], acc[mi][4 * ksp + 0][3] + bb1[0]);
                w1.y = packf16(acc[mi][4 * ksp + 1][2] + bb0[1], acc[mi][4 * ksp + 1][3] + bb1[1]);
                w1.z = packf16(acc[mi][4 * ksp + 2][2] + bb0[2], acc[mi][4 * ksp + 2][3] + bb1[2]);
                w1.w = packf16(acc[mi][4 * ksp + 3][2] + bb0[3], acc[mi][4 * ksp + 3][3] + bb1[3]);
                Kq[base + ((size_t)(nt0 * 2 + ksp)) * 32 + lane] = w0;
                Kq[base + ((size_t)((nt0 + 1) * 2 + ksp)) * 32 + lane] = w1;
            }
        }
    } else {
        unsigned short* sT = (unsigned short*)ps;
#pragma unroll
        for (int mi = 0; mi < 2; ++mi) {
            const int r0 = wm * 32 + mi * 16 + g;
#pragma unroll
            for (int ni = 0; ni < 8; ++ni) {
                const int c = wn * 64 + ni * 8 + 2 * t;
                const float b0 = bias[bn + c];
                const float b1 = bias[bn + c + 1];
                *(uint32_t*)&sT[r0 * 136 + c]       = packf16(acc[mi][ni][0] + b0, acc[mi][ni][1] + b1);
                *(uint32_t*)&sT[(r0 + 8) * 136 + c] = packf16(acc[mi][ni][2] + b0, acc[mi][ni][3] + b1);
            }
        }
        __syncthreads();

        const int bb   = bm >> 11;
        const int tokb = bm & 2047;
#pragma unroll
        for (int i = 0; i < 8; ++i) {
            const int q6   = i * 8 + (tid >> 5);
            const int head = q6 >> 5;
            const int kt2  = (q6 >> 4) & 1;
            const int kp   = (q6 >> 2) & 3;
            const int nd2  = q6 & 3;
            const int r0 = kt2 * 64 + kp * 16 + 2 * t;
            const int c0 = head * 64 + nd2 * 16 + g;
            uint4 w;
            w.x = (uint32_t)sT[r0 * 136 + c0]           | ((uint32_t)sT[(r0 + 1) * 136 + c0] << 16);
            w.y = (uint32_t)sT[(r0 + 8) * 136 + c0]     | ((uint32_t)sT[(r0 + 9) * 136 + c0] << 16);
            w.z = (uint32_t)sT[r0 * 136 + c0 + 8]       | ((uint32_t)sT[(r0 + 1) * 136 + c0 + 8] << 16);
            w.w = (uint32_t)sT[(r0 + 8) * 136 + c0 + 8] | ((uint32_t)sT[(r0 + 9) * 136 + c0 + 8] << 16);
            const int hg  = (blockIdx.x - 16) * 2 + head;
            const int ktg = (tokb >> 6) + kt2;
            Vq[((size_t)(bb * Hh + hg) * 32 + ktg) * 512 + (kp * 4 + nd2) * 32 + lane] = w;
        }
    }
}

// ===========================================================================
// Flash attention (round-11 shape): 128 threads / 64 queries per CTA,
// 2-stage cp.async, all-fp16 MMA. Softmax: ex2.approx.f16x2 (MUFU halved),
// row-sum l via ones-B MMA on the same fp16 P fragments.
// ===========================================================================
#define ATTN_SMEM_BYTES (2 * 8192 + 2 * 8192 + 2 * 256)
#define C1 0.18033688011112042f   // 0.125 * log2(e)
#define ONESF16X2 0x3C003C00u     // (1.0h, 1.0h)

__global__ void __launch_bounds__(128, 3)
attn_kernel(const uint4* __restrict__ Qp, uint4* __restrict__ Opacked)
{
    extern __shared__ uint4 asm4[];
    uint4* sK = asm4;                      // [2][512]
    uint4* sV = asm4 + 1024;               // [2][512]
    float* sBias = (float*)(asm4 + 2048);  // [2][64]

    const uint32_t sKaddr = smem_u32(sK);
    const uint32_t sVaddr = smem_u32(sV);
    const uint32_t sBaddr = smem_u32(sBias);

    const int qt = blockIdx.x;
    const int h  = blockIdx.y;
    const int b  = blockIdx.z;
    const int tid  = threadIdx.x;
    const int warp = tid >> 5;
    const int lane = tid & 31;
    const int t = lane & 3;

    const size_t kvBase = ((size_t)(b * Hh + h)) * 32 * 512;
    const int R = (b * Ts + qt * 64 + warp * 16) >> 4;

    // Q fragments straight from the A-pack
    uint4 qf[4];
#pragma unroll
    for (int ks = 0; ks < 4; ++ks)
        qf[ks] = Qp[((size_t)R * 64 + h * 4 + ks) * 32 + lane];

    float o[8][4];
#pragma unroll
    for (int i = 0; i < 8; ++i)
#pragma unroll
        for (int j = 0; j < 4; ++j) o[i][j] = 0.f;
    float lacc[4] = {0.f, 0.f, 0.f, 0.f};   // ones-B MMA accumulator (row sums)

    auto issue = [&](int buf, int kt) {
        const uint4* srcK = g_Kq + kvBase + (size_t)kt * 512 + tid;
        const uint4* srcV = g_Vq + kvBase + (size_t)kt * 512 + tid;
        const uint32_t dK = sKaddr + buf * 8192 + tid * 16;
        const uint32_t dV = sVaddr + buf * 8192 + tid * 16;
#pragma unroll
        for (int i = 0; i < 4; ++i) {
            cp_async16(dK + i * 2048, srcK + i * 128);
            cp_async16(dV + i * 2048, srcV + i * 128);
        }
        if (tid < 16) cp_async16(sBaddr + buf * 256 + tid * 16, g_bias + b * Ts + kt * 64 + tid * 4);
    };

    issue(0, 0);
    CP_COMMIT();

    for (int kt = 0; kt < Ts / 64; ++kt) {
        const int buf = kt & 1;
        if (kt + 1 < Ts / 64) {
            issue(buf ^ 1, kt + 1);
            CP_COMMIT();
            CP_WAIT(1);
        } else {
            CP_WAIT(0);
        }
        __syncthreads();

        const uint4* bK = sK + buf * 512;
        const uint4* bV = sV + buf * 512;
        const float* bB = sBias + buf * 64;

        // ---- S = Q K^T (fp16) ----
        float sacc[8][4];
#pragma unroll
        for (int nt = 0; nt < 8; ++nt)
#pragma unroll
            for (int j = 0; j < 4; ++j) sacc[nt][j] = 0.f;
#pragma unroll
        for (int ksp = 0; ksp < 2; ++ksp) {
#pragma unroll
            for (int nt = 0; nt < 8; ++nt) {
                const uint4 f = bK[(nt * 2 + ksp) * 32 + lane];
                mma_f16q(sacc[nt], qf[2 * ksp], f.x, f.y);
                mma_f16q(sacc[nt], qf[2 * ksp + 1], f.z, f.w);
            }
        }

        // ---- softmax weights: P = exp2(S*C1 + log2bias) on MUFU f16x2 ----
        uint32_t ph[8][2];
#pragma unroll
        for (int nt = 0; nt < 8; ++nt) {
            const float2 bb2 = *(const float2*)(bB + 8 * nt + 2 * t);
            const float a0 = fmaf(sacc[nt][0], C1, bb2.x);
            const float a1 = fmaf(sacc[nt][1], C1, bb2.y);
            const float a2 = fmaf(sacc[nt][2], C1, bb2.x);
            const float a3 = fmaf(sacc[nt][3], C1, bb2.y);
            ph[nt][0] = ex2_f16x2(packf16(a0, a1));
            ph[nt][1] = ex2_f16x2(packf16(a2, a3));
        }

        // ---- O += P V (fp16); l += P @ ones ----
#pragma unroll
        for (int kp = 0; kp < 4; ++kp) {
            const uint32_t a[4] = { ph[2 * kp][0], ph[2 * kp][1],
                                    ph[2 * kp + 1][0], ph[2 * kp + 1][1] };
            mma_f16(lacc, a, ONESF16X2, ONESF16X2);
#pragma unroll
            for (int nd2 = 0; nd2 < 4; ++nd2) {
                const uint4 f = bV[(kp * 4 + nd2) * 32 + lane];
                mma_f16(o[2 * nd2], a, f.x, f.y);
                mma_f16(o[2 * nd2 + 1], a, f.z, f.w);
            }
        }
        __syncthreads();
    }

    // ones-B MMA: every output column equals the full row sum -> no shuffles
    const float inv0 = 1.0f / lacc[0];
    const float inv1 = 1.0f / lacc[2];

    // fused epilogue: normalize + write fp16 A-pack quads
#pragma unroll
    for (int sd = 0; sd < 4; ++sd) {
        uint4 w;
        w.x = packf16(o[2 * sd][0] * inv0,     o[2 * sd][1] * inv0);
        w.y = packf16(o[2 * sd][2] * inv1,     o[2 * sd][3] * inv1);
        w.z = packf16(o[2 * sd + 1][0] * inv0, o[2 * sd + 1][1] * inv0);
        w.w = packf16(o[2 * sd + 1][2] * inv1, o[2 * sd + 1][3] * inv1);
        Opacked[((size_t)R * 64 + h * 4 + sd) * 32 + lane] = w;
    }
}

// ===========================================================================
extern "C" void kernel_launch(void* const* d_in, const int* in_sizes, int n_in,
                              void* d_out, int out_size)
{
    const float* x     = (const float*)d_in[0];
    const float* eng   = (const float*)d_in[1];
    const void*  mask  = (const void*)d_in[2];
    const float* qkv_w = (const float*)d_in[3];
    const float* qkv_b = (const float*)d_in[4];
    const float* out_w = (const float*)d_in[5];
    const float* out_b = (const float*)d_in[6];
    float* out = (float*)d_out;

    uint4 *qp = nullptr, *kq = nullptr, *vq = nullptr;
    uint4 *xp = nullptr, *op = nullptr, *wq = nullptr, *wo = nullptr;
    cudaGetSymbolAddress((void**)&qp, g_qp);
    cudaGetSymbolAddress((void**)&kq, g_Kq);
    cudaGetSymbolAddress((void**)&vq, g_Vq);
    cudaGetSymbolAddress((void**)&xp, g_xp);
    cudaGetSymbolAddress((void**)&op, g_op);
    cudaGetSymbolAddress((void**)&wq, g_wq);
    cudaGetSymbolAddress((void**)&wo, g_wo);

    cudaFuncSetAttribute(f16_gemm_packed,
                         cudaFuncAttributeMaxDynamicSharedMemorySize, GP_SMEM_BYTES);
    cudaFuncSetAttribute(qkv_gemm_fused,
                         cudaFuncAttributeMaxDynamicSharedMemorySize, GP_SMEM_BYTES);
    cudaFuncSetAttribute(attn_kernel,
                         cudaFuncAttributeMaxDynamicSharedMemorySize, ATTN_SMEM_BYTES);

    // 0) mask dtype detection + per-key bias precompute (log2 domain)
    detect_mask_kernel<<<1, 256>>>((const unsigned char*)mask);
    bias_kernel<<<(Bb * Ts + 255) / 256, 256>>>(eng, mask);

    // 0b) pack x and weights into fp16 fragment layouts
    pack_a_f16<<<2048, 256>>>(x, xp, M_ROWS, Dd);
    pack_b_f16<<<1536, 256>>>(qkv_w, wq, QKV_N, Dd);
    pack_b_f16<<<512, 256>>>(out_w, wo, Dd, Dd);

    // 1) fused QKV projection -> Q A-pack, K B-pack, V frag tiles
    dim3 g1(QKV_N / 128, M_ROWS / 128);
    qkv_gemm_fused<<<g1, 256, GP_SMEM_BYTES>>>(xp, wq, qkv_b, qp, kq, vq);

    // 2) attention (all-fp16 MMA, f16x2 MUFU softmax) -> fp16 A-pack
    dim3 g2(Ts / 64, Hh, Bb);
    attn_kernel<<<g2, 128, ATTN_SMEM_BYTES>>>(qp, op);

    // 3) output projection (packed fp16 mma.sync, 4-stage pipeline)
    dim3 g3(Dd / 128, M_ROWS / 128);
    f16_gemm_packed<<<g3, 256, GP_SMEM_BYTES>>>(op, wo, out_b, out, Dd, Dd);
}

// round 14
// speedup vs baseline: 1.0477x; 1.0434x over previous
#include <cuda_runtime.h>
#include <cuda_bf16.h>
#include <cuda_fp16.h>
#include <math.h>
#include <stdint.h>

// Problem constants
#define Bb 4
#define Ts 2048
#define Dd 1024
#define Hh 16
#define HD 64
#define M_ROWS 8192
#define QKV_N 3072

// Scratch (device globals: allocation-free)
__device__ float g_bias[Bb * Ts];                 // per-key log2-domain bias
__device__ int   g_maskMode;
// Fragment-ready fp16 buffers
__device__ uint4 g_qp[(size_t)(M_ROWS / 16) * 64 * 32];   // Q A-pack
__device__ uint4 g_Kq[(size_t)Bb * Hh * 32 * 512];        // K B-pack tiles
__device__ uint4 g_Vq[(size_t)Bb * Hh * 32 * 512];        // V frag tiles
__device__ uint4 g_xp[(size_t)(M_ROWS / 16) * 64 * 32];   // x A-pack
__device__ uint4 g_op[(size_t)(M_ROWS / 16) * 64 * 32];   // attn-out A-pack
__device__ uint4 g_wq[(size_t)(QKV_N / 8) * 32 * 32];     // qkv_w B-pack
__device__ uint4 g_wo[(size_t)(Dd / 8) * 32 * 32];        // out_w B-pack

// ===========================================================================
// helpers
// ===========================================================================
__device__ __forceinline__ uint32_t packf16(float lo, float hi) {
    uint32_t r;
    asm("cvt.rn.f16x2.f32 %0, %1, %2;" : "=r"(r) : "f"(hi), "f"(lo));
    return r;
}
__device__ __forceinline__ uint32_t ex2_f16x2(uint32_t x) {
    uint32_t r;
    asm("ex2.approx.f16x2 %0, %1;" : "=r"(r) : "r"(x));
    return r;
}

__device__ __forceinline__ void mma_f16(float* c, const uint32_t* a, uint32_t b0, uint32_t b1) {
    asm volatile(
        "mma.sync.aligned.m16n8k16.row.col.f32.f16.f16.f32 "
        "{%0,%1,%2,%3}, {%4,%5,%6,%7}, {%8,%9}, {%0,%1,%2,%3};\n"
        : "+f"(c[0]), "+f"(c[1]), "+f"(c[2]), "+f"(c[3])
        : "r"(a[0]), "r"(a[1]), "r"(a[2]), "r"(a[3]), "r"(b0), "r"(b1));
}
__device__ __forceinline__ void mma_f16q(float* c, const uint4& a, uint32_t b0, uint32_t b1) {
    asm volatile(
        "mma.sync.aligned.m16n8k16.row.col.f32.f16.f16.f32 "
        "{%0,%1,%2,%3}, {%4,%5,%6,%7}, {%8,%9}, {%0,%1,%2,%3};\n"
        : "+f"(c[0]), "+f"(c[1]), "+f"(c[2]), "+f"(c[3])
        : "r"(a.x), "r"(a.y), "r"(a.z), "r"(a.w), "r"(b0), "r"(b1));
}

__device__ __forceinline__ uint32_t smem_u32(const void* p) {
    uint32_t a;
    asm("{ .reg .u64 t; cvta.to.shared.u64 t, %1; cvt.u32.u64 %0, t; }" : "=r"(a) : "l"(p));
    return a;
}
__device__ __forceinline__ void cp_async16(uint32_t dst, const void* src) {
    asm volatile("cp.async.cg.shared.global [%0], [%1], 16;" :: "r"(dst), "l"(src));
}
#define CP_COMMIT() asm volatile("cp.async.commit_group;" ::: "memory")
#define CP_WAIT(n)  asm volatile("cp.async.wait_group %0;" :: "n"(n) : "memory")

// ===========================================================================
// Mask dtype detection + bias precompute (log2 domain)
// ===========================================================================
__global__ void detect_mask_kernel(const unsigned char* __restrict__ mask)
{
    __shared__ unsigned int orr[4][256];
    const int tid = threadIdx.x;
    unsigned int o0 = 0, o1 = 0, o2 = 0, o3 = 0;
    for (int i = tid * 4; i < Bb * Ts; i += 256 * 4) {
        o0 |= mask[i + 0]; o1 |= mask[i + 1]; o2 |= mask[i + 2]; o3 |= mask[i + 3];
    }
    orr[0][tid] = o0; orr[1][tid] = o1; orr[2][tid] = o2; orr[3][tid] = o3;
    __syncthreads();
    for (int s = 128; s; s >>= 1) {
        if (tid < s) {
            orr[0][tid] |= orr[0][tid + s];
            orr[1][tid] |= orr[1][tid + s];
            orr[2][tid] |= orr[2][tid + s];
            orr[3][tid] |= orr[3][tid + s];
        }
        __syncthreads();
    }
    if (tid == 0) {
        unsigned int l0 = orr[0][0], l1 = orr[1][0], l2 = orr[2][0], l3 = orr[3][0];
        int mode;
        if ((l1 | l2 | l3) == 0u) mode = 1;
        else if ((l0 | l1) == 0u && (l2 | l3) != 0u) mode = 2;
        else mode = 0;
        g_maskMode = mode;
    }
}

__global__ void bias_kernel(const float* __restrict__ eng, const void* __restrict__ mask)
{
    const int kk = blockIdx.x * 256 + threadIdx.x;
    if (kk >= Bb * Ts) return;
    const int mode = g_maskMode;
    bool m;
    if (mode == 1)      m = ((const int*)mask)[kk] != 0;
    else if (mode == 2) m = ((const float*)mask)[kk] != 0.f;
    else                m = ((const unsigned char*)mask)[kk] != 0;
    g_bias[kk] = m ? -1e9f : log2f(fmaxf(eng[kk], 1e-6f));
}

// ===========================================================================
// fp16 fragment packing (A- and B-layouts)
// ===========================================================================
__global__ void __launch_bounds__(256)
pack_a_f16(const float* __restrict__ src, uint4* __restrict__ dst, int M, int K)
{
    const int K16 = K >> 4;
    const int total = (M >> 4) * K16 * 32;
    for (int q = blockIdx.x * 256 + threadIdx.x; q < total; q += gridDim.x * 256) {
        const int lane = q & 31;
        const int rs = q >> 5;
        const int S = rs % K16;
        const int R = rs / K16;
        const int g = lane >> 2, t = lane & 3;
        const float* p = src + (size_t)(R * 16 + g) * K + S * 16 + 2 * t;
        const float* p2 = p + (size_t)8 * K;
        const float2 a0 = *(const float2*)(p);
        const float2 a1 = *(const float2*)(p2);
        const float2 a2 = *(const float2*)(p + 8);
        const float2 a3 = *(const float2*)(p2 + 8);
        uint4 w;
        w.x = packf16(a0.x, a0.y);
        w.y = packf16(a1.x, a1.y);
        w.z = packf16(a2.x, a2.y);
        w.w = packf16(a3.x, a3.y);
        dst[q] = w;
    }
}

__global__ void __launch_bounds__(256)
pack_b_f16(const float* __restrict__ src, uint4* __restrict__ dst, int N, int K)
{
    const int K32 = K >> 5;
    const int total = (N >> 3) * K32 * 32;
    for (int q = blockIdx.x * 256 + threadIdx.x; q < total; q += gridDim.x * 256) {
        const int lane = q & 31;
        const int cs = q >> 5;
        const int S = cs % K32;
        const int C = cs / K32;
        const int g = lane >> 2, t = lane & 3;
        const float* p = src + (size_t)(C * 8 + g) * K + S * 32 + 2 * t;
        const float2 b0 = *(const float2*)(p);
        const float2 b1 = *(const float2*)(p + 8);
        const float2 b2 = *(const float2*)(p + 16);
        const float2 b3 = *(const float2*)(p + 24);
        uint4 w;
        w.x = packf16(b0.x, b0.y);
        w.y = packf16(b1.x, b1.y);
        w.z = packf16(b2.x, b2.y);
        w.w = packf16(b3.x, b3.y);
        dst[q] = w;
    }
}

// ===========================================================================
// GEMM: 128x128 tile, BK=32, 4-stage cp.async.
// ===========================================================================
#define GP_SMEM_BYTES 65536

__global__ void __launch_bounds__(256)
f16_gemm_packed(const uint4* __restrict__ Ap, const uint4* __restrict__ Bp,
                const float* __restrict__ bias, float* __restrict__ C,
                int K, int ldc)
{
    extern __shared__ uint4 ps[];
    uint4* sA = ps;
    uint4* sB = ps + 2048;
    const uint32_t sAaddr = smem_u32(sA);
    const uint32_t sBaddr = smem_u32(sB);

    const int tid  = threadIdx.x;
    const int wid  = tid >> 5;
    const int lane = tid & 31;
    const int g = lane >> 2, t = lane & 3;
    const int wm = wid & 3;
    const int wn = wid >> 2;
    const int bm = blockIdx.y * 128;
    const int bn = blockIdx.x * 128;
    const int K16 = K >> 4;
    const int K32 = K >> 5;
    const int Rb = bm >> 4;
    const int Cb = bn >> 3;

    float acc[2][8][4];
#pragma unroll
    for (int mi = 0; mi < 2; ++mi)
#pragma unroll
        for (int ni = 0; ni < 8; ++ni)
#pragma unroll
            for (int r = 0; r < 4; ++r) acc[mi][ni][r] = 0.f;

    auto issue = [&](int buf, int kt) {
#pragma unroll
        for (int i = 0; i < 2; ++i) {
            const int l    = tid + 256 * i;
            const int tile = l >> 5;
            const int ln   = l & 31;
            cp_async16(sAaddr + buf * 8192 + l * 16,
                       Ap + ((size_t)(Rb + (tile >> 1)) * K16 + 2 * kt + (tile & 1)) * 32 + ln);
            cp_async16(sBaddr + buf * 8192 + l * 16,
                       Bp + ((size_t)(Cb + tile) * K32 + kt) * 32 + ln);
        }
    };

    const int nChunks = K >> 5;
#pragma unroll
    for (int p = 0; p < 3; ++p) {
        if (p < nChunks) { issue(p, p); CP_COMMIT(); }
    }

    for (int kt = 0; kt < nChunks; ++kt) {
        if (kt + 3 < nChunks) {
            issue((kt + 3) & 3, kt + 3);
            CP_COMMIT();
            CP_WAIT(3);
        } else if (kt + 2 < nChunks) { CP_WAIT(2); }
        else if (kt + 1 < nChunks)   { CP_WAIT(1); }
        else                         { CP_WAIT(0); }
        __syncthreads();

        const uint4* bufA = sA + (kt & 3) * 512;
        const uint4* bufB = sB + (kt & 3) * 512;
        uint4 fa[2][2];
#pragma unroll
        for (int mi = 0; mi < 2; ++mi)
#pragma unroll
            for (int kc = 0; kc < 2; ++kc)
                fa[mi][kc] = bufA[(((wm * 2 + mi) << 1) | kc) * 32 + lane];
#pragma unroll
        for (int ni = 0; ni < 8; ++ni) {
            const uint4 f = bufB[(wn * 8 + ni) * 32 + lane];
            mma_f16q(acc[0][ni], fa[0][0], f.x, f.y);
            mma_f16q(acc[1][ni], fa[1][0], f.x, f.y);
            mma_f16q(acc[0][ni], fa[0][1], f.z, f.w);
            mma_f16q(acc[1][ni], fa[1][1], f.z, f.w);
        }
        __syncthreads();
    }

#pragma unroll
    for (int mi = 0; mi < 2; ++mi) {
        const int row = bm + wm * 32 + mi * 16 + g;
#pragma unroll
        for (int ni = 0; ni < 8; ++ni) {
            const int col = bn + wn * 64 + ni * 8 + 2 * t;
            const float b0 = bias[col];
            const float b1 = bias[col + 1];
            float2 lo, hi;
            lo.x = acc[mi][ni][0] + b0; lo.y = acc[mi][ni][1] + b1;
            hi.x = acc[mi][ni][2] + b0; hi.y = acc[mi][ni][3] + b1;
            *(float2*)(C + (size_t)row * ldc + col) = lo;
            *(float2*)(C + (size_t)(row + 8) * ldc + col) = hi;
        }
    }
}

// ===========================================================================
// Fused QKV GEMM (unchanged from round 11)
// ===========================================================================
__global__ void __launch_bounds__(256)
qkv_gemm_fused(const uint4* __restrict__ Ap, const uint4* __restrict__ Bp,
               const float* __restrict__ bias,
               uint4* __restrict__ Qp, uint4* __restrict__ Kq, uint4* __restrict__ Vq)
{
    extern __shared__ uint4 ps[];
    uint4* sA = ps;
    uint4* sB = ps + 2048;
    const uint32_t sAaddr = smem_u32(sA);
    const uint32_t sBaddr = smem_u32(sB);

    const int tid  = threadIdx.x;
    const int wid  = tid >> 5;
    const int lane = tid & 31;
    const int g = lane >> 2, t = lane & 3;
    const int wm = wid & 3;
    const int wn = wid >> 2;
    const int bm = blockIdx.y * 128;
    const int bn = blockIdx.x * 128;
    const int K16 = Dd >> 4;
    const int K32 = Dd >> 5;
    const int Rb = bm >> 4;
    const int Cb = bn >> 3;

    float acc[2][8][4];
#pragma unroll
    for (int mi = 0; mi < 2; ++mi)
#pragma unroll
        for (int ni = 0; ni < 8; ++ni)
#pragma unroll
            for (int r = 0; r < 4; ++r) acc[mi][ni][r] = 0.f;

    auto issue = [&](int buf, int kt) {
#pragma unroll
        for (int i = 0; i < 2; ++i) {
            const int l    = tid + 256 * i;
            const int tile = l >> 5;
            const int ln   = l & 31;
            cp_async16(sAaddr + buf * 8192 + l * 16,
                       Ap + ((size_t)(Rb + (tile >> 1)) * K16 + 2 * kt + (tile & 1)) * 32 + ln);
            cp_async16(sBaddr + buf * 8192 + l * 16,
                       Bp + ((size_t)(Cb + tile) * K32 + kt) * 32 + ln);
        }
    };

    const int nChunks = Dd >> 5;
#pragma unroll
    for (int p = 0; p < 3; ++p) { issue(p, p); CP_COMMIT(); }

    for (int kt = 0; kt < nChunks; ++kt) {
        if (kt + 3 < nChunks) {
            issue((kt + 3) & 3, kt + 3);
            CP_COMMIT();
            CP_WAIT(3);
        } else if (kt + 2 < nChunks) { CP_WAIT(2); }
        else if (kt + 1 < nChunks)   { CP_WAIT(1); }
        else                         { CP_WAIT(0); }
        __syncthreads();

        const uint4* bufA = sA + (kt & 3) * 512;
        const uint4* bufB = sB + (kt & 3) * 512;
        uint4 fa[2][2];
#pragma unroll
        for (int mi = 0; mi < 2; ++mi)
#pragma unroll
            for (int kc = 0; kc < 2; ++kc)
                fa[mi][kc] = bufA[(((wm * 2 + mi) << 1) | kc) * 32 + lane];
#pragma unroll
        for (int ni = 0; ni < 8; ++ni) {
            const uint4 f = bufB[(wn * 8 + ni) * 32 + lane];
            mma_f16q(acc[0][ni], fa[0][0], f.x, f.y);
            mma_f16q(acc[1][ni], fa[1][0], f.x, f.y);
            mma_f16q(acc[0][ni], fa[0][1], f.z, f.w);
            mma_f16q(acc[1][ni], fa[1][1], f.z, f.w);
        }
        __syncthreads();
    }

    const int region = blockIdx.x >> 3;

    if (region == 0) {
#pragma unroll
        for (int mi = 0; mi < 2; ++mi) {
            const int R = Rb + wm * 2 + mi;
#pragma unroll
            for (int s = 0; s < 4; ++s) {
                const int colb = bn + wn * 64 + s * 16;
                const float b0 = bias[colb + 2 * t];
                const float b1 = bias[colb + 2 * t + 1];
                const float b2 = bias[colb + 8 + 2 * t];
                const float b3 = bias[colb + 8 + 2 * t + 1];
                uint4 w;
                w.x = packf16(acc[mi][2 * s][0] + b0,     acc[mi][2 * s][1] + b1);
                w.y = packf16(acc[mi][2 * s][2] + b0,     acc[mi][2 * s][3] + b1);
                w.z = packf16(acc[mi][2 * s + 1][0] + b2, acc[mi][2 * s + 1][1] + b3);
                w.w = packf16(acc[mi][2 * s + 1][2] + b2, acc[mi][2 * s + 1][3] + b3);
                const int Scol = blockIdx.x * 8 + wn * 4 + s;
                Qp[((size_t)R * 64 + Scol) * 32 + lane] = w;
            }
        }
    } else if (region == 1) {
        const int h = (blockIdx.x - 8) * 2 + wn;
#pragma unroll
        for (int mi = 0; mi < 2; ++mi) {
            const int rowbase = bm + wm * 32 + mi * 16;
            const int bb  = rowbase >> 11;
            const int tok = rowbase & 2047;
            const int kt  = tok >> 6;
            const int nt0 = (tok >> 3) & 7;
            const size_t base = ((size_t)(bb * Hh + h) * 32 + kt) * 512;
#pragma unroll
            for (int ksp = 0; ksp < 2; ++ksp) {
                const int colb = bn + wn * 64 + 32 * ksp;
                float bb0[4], bb1[4];
#pragma unroll
                for (int j = 0; j < 4; ++j) {
                    bb0[j] = bias[colb + 8 * j + 2 * t];
                    bb1[j] = bias[colb + 8 * j + 2 * t + 1];
                }
                uint4 w0, w1;
                w0.x = packf16(acc[mi][4 * ksp + 0][0] + bb0[0], acc[mi][4 * ksp + 0][1] + bb1[0]);
                w0.y = packf16(acc[mi][4 * ksp + 1][0] + bb0[1], acc[mi][4 * ksp + 1][1] + bb1[1]);
                w0.z = packf16(acc[mi][4 * ksp + 2][0] + bb0[2], acc[mi][4 * ksp + 2][1] + bb1[2]);
                w0.w = packf16(acc[mi][4 * ksp + 3][0] + bb0[3], acc[mi][4 * ksp + 3][1] + bb1[3]);
                w1.x = packf16(acc[mi][4 * ksp + 0][2] + bb0[0], acc[mi][4 * ksp + 0][3] + bb1[0]);
                w1.y = packf16(acc[mi][4 * ksp + 1][2] + bb0[1], acc[mi][4 * ksp + 1][3] + bb1[1]);
                w1.z = packf16(acc[mi][4 * ksp + 2][2] + bb0[2], acc[mi][4 * ksp + 2][3] + bb1[2]);
                w1.w = packf16(acc[mi][4 * ksp + 3][2] + bb0[3], acc[mi][4 * ksp + 3][3] + bb1[3]);
                Kq[base + ((size_t)(nt0 * 2 + ksp)) * 32 + lane] = w0;
                Kq[base + ((size_t)((nt0 + 1) * 2 + ksp)) * 32 + lane] = w1;
            }
        }
    } else {
        unsigned short* sT = (unsigned short*)ps;
#pragma unroll
        for (int mi = 0; mi < 2; ++mi) {
            const int r0 = wm * 32 + mi * 16 + g;
#pragma unroll
            for (int ni = 0; ni < 8; ++ni) {
                const int c = wn * 64 + ni * 8 + 2 * t;
                const float b0 = bias[bn + c];
                const float b1 = bias[bn + c + 1];
                *(uint32_t*)&sT[r0 * 136 + c]       = packf16(acc[mi][ni][0] + b0, acc[mi][ni][1] + b1);
                *(uint32_t*)&sT[(r0 + 8) * 136 + c] = packf16(acc[mi][ni][2] + b0, acc[mi][ni][3] + b1);
            }
        }
        __syncthreads();

        const int bb   = bm >> 11;
        const int tokb = bm & 2047;
#pragma unroll
        for (int i = 0; i < 8; ++i) {
            const int q6   = i * 8 + (tid >> 5);
            const int head = q6 >> 5;
            const int kt2  = (q6 >> 4) & 1;
            const int kp   = (q6 >> 2) & 3;
            const int nd2  = q6 & 3;
            const int r0 = kt2 * 64 + kp * 16 + 2 * t;
            const int c0 = head * 64 + nd2 * 16 + g;
            uint4 w;
            w.x = (uint32_t)sT[r0 * 136 + c0]           | ((uint32_t)sT[(r0 + 1) * 136 + c0] << 16);
            w.y = (uint32_t)sT[(r0 + 8) * 136 + c0]     | ((uint32_t)sT[(r0 + 9) * 136 + c0] << 16);
            w.z = (uint32_t)sT[r0 * 136 + c0 + 8]       | ((uint32_t)sT[(r0 + 1) * 136 + c0 + 8] << 16);
            w.w = (uint32_t)sT[(r0 + 8) * 136 + c0 + 8] | ((uint32_t)sT[(r0 + 9) * 136 + c0 + 8] << 16);
            const int hg  = (blockIdx.x - 16) * 2 + head;
            const int ktg = (tokb >> 6) + kt2;
            Vq[((size_t)(bb * Hh + hg) * 32 + ktg) * 512 + (kp * 4 + nd2) * 32 + lane] = w;
        }
    }
}

// ===========================================================================
// Flash attention: 32 queries PER WARP (two A-frags), 128 queries / 128-thread
// CTA -> each K/V LDS.128 feeds 4 MMAs (smem crossbar traffic halved).
// 2-stage cp.async, ex2.f16x2 softmax, ones-B MMA row sums.
// ===========================================================================
#define ATTN_SMEM_BYTES (2 * 8192 + 2 * 8192 + 2 * 256)
#define C1 0.18033688011112042f   // 0.125 * log2(e)
#define ONESF16X2 0x3C003C00u     // (1.0h, 1.0h)

__global__ void __launch_bounds__(128, 2)
attn_kernel(const uint4* __restrict__ Qp, uint4* __restrict__ Opacked)
{
    extern __shared__ uint4 asm4[];
    uint4* sK = asm4;                      // [2][512]
    uint4* sV = asm4 + 1024;               // [2][512]
    float* sBias = (float*)(asm4 + 2048);  // [2][64]

    const uint32_t sKaddr = smem_u32(sK);
    const uint32_t sVaddr = smem_u32(sV);
    const uint32_t sBaddr = smem_u32(sBias);

    const int qt = blockIdx.x;     // 128-query tile
    const int h  = blockIdx.y;
    const int b  = blockIdx.z;
    const int tid  = threadIdx.x;
    const int warp = tid >> 5;     // 0..3, owns 32 queries
    const int lane = tid & 31;
    const int t = lane & 3;

    const size_t kvBase = ((size_t)(b * Hh + h)) * 32 * 512;
    const int R0 = (b * Ts + qt * 128 + warp * 32) >> 4;   // two R-tiles: R0, R0+1

    // Q fragments for both query halves, straight from the A-pack
    uint4 qf[2][4];
#pragma unroll
    for (int hf = 0; hf < 2; ++hf)
#pragma unroll
        for (int ks = 0; ks < 4; ++ks)
            qf[hf][ks] = Qp[((size_t)(R0 + hf) * 64 + h * 4 + ks) * 32 + lane];

    float o[2][8][4];
#pragma unroll
    for (int hf = 0; hf < 2; ++hf)
#pragma unroll
        for (int i = 0; i < 8; ++i)
#pragma unroll
            for (int j = 0; j < 4; ++j) o[hf][i][j] = 0.f;
    float lacc[2][4] = {{0.f, 0.f, 0.f, 0.f}, {0.f, 0.f, 0.f, 0.f}};

    auto issue = [&](int buf, int kt) {
        const uint4* srcK = g_Kq + kvBase + (size_t)kt * 512 + tid;
        const uint4* srcV = g_Vq + kvBase + (size_t)kt * 512 + tid;
        const uint32_t dK = sKaddr + buf * 8192 + tid * 16;
        const uint32_t dV = sVaddr + buf * 8192 + tid * 16;
#pragma unroll
        for (int i = 0; i < 4; ++i) {
            cp_async16(dK + i * 2048, srcK + i * 128);
            cp_async16(dV + i * 2048, srcV + i * 128);
        }
        if (tid < 16) cp_async16(sBaddr + buf * 256 + tid * 16, g_bias + b * Ts + kt * 64 + tid * 4);
    };

    issue(0, 0);
    CP_COMMIT();

    for (int kt = 0; kt < Ts / 64; ++kt) {
        const int buf = kt & 1;
        if (kt + 1 < Ts / 64) {
            issue(buf ^ 1, kt + 1);
            CP_COMMIT();
            CP_WAIT(1);
        } else {
            CP_WAIT(0);
        }
        __syncthreads();

        const uint4* bK = sK + buf * 512;
        const uint4* bV = sV + buf * 512;
        const float* bB = sBias + buf * 64;

        // ---- S = Q K^T (fp16), both query halves share each K quad ----
        float sacc[2][8][4];
#pragma unroll
        for (int hf = 0; hf < 2; ++hf)
#pragma unroll
            for (int nt = 0; nt < 8; ++nt)
#pragma unroll
                for (int j = 0; j < 4; ++j) sacc[hf][nt][j] = 0.f;
#pragma unroll
        for (int ksp = 0; ksp < 2; ++ksp) {
#pragma unroll
            for (int nt = 0; nt < 8; ++nt) {
                const uint4 f = bK[(nt * 2 + ksp) * 32 + lane];
                mma_f16q(sacc[0][nt], qf[0][2 * ksp], f.x, f.y);
                mma_f16q(sacc[0][nt], qf[0][2 * ksp + 1], f.z, f.w);
                mma_f16q(sacc[1][nt], qf[1][2 * ksp], f.x, f.y);
                mma_f16q(sacc[1][nt], qf[1][2 * ksp + 1], f.z, f.w);
            }
        }

        // ---- softmax weights: P = exp2(S*C1 + log2bias) on MUFU f16x2 ----
        uint32_t ph[2][8][2];
#pragma unroll
        for (int nt = 0; nt < 8; ++nt) {
            const float2 bb2 = *(const float2*)(bB + 8 * nt + 2 * t);
#pragma unroll
            for (int hf = 0; hf < 2; ++hf) {
                const float a0 = fmaf(sacc[hf][nt][0], C1, bb2.x);
                const float a1 = fmaf(sacc[hf][nt][1], C1, bb2.y);
                const float a2 = fmaf(sacc[hf][nt][2], C1, bb2.x);
                const float a3 = fmaf(sacc[hf][nt][3], C1, bb2.y);
                ph[hf][nt][0] = ex2_f16x2(packf16(a0, a1));
                ph[hf][nt][1] = ex2_f16x2(packf16(a2, a3));
            }
        }

        // ---- O += P V (fp16); l += P @ ones; V quads shared by both halves ----
#pragma unroll
        for (int kp = 0; kp < 4; ++kp) {
            const uint32_t a0[4] = { ph[0][2 * kp][0], ph[0][2 * kp][1],
                                     ph[0][2 * kp + 1][0], ph[0][2 * kp + 1][1] };
            const uint32_t a1[4] = { ph[1][2 * kp][0], ph[1][2 * kp][1],
                                     ph[1][2 * kp + 1][0], ph[1][2 * kp + 1][1] };
            mma_f16(lacc[0], a0, ONESF16X2, ONESF16X2);
            mma_f16(lacc[1], a1, ONESF16X2, ONESF16X2);
#pragma unroll
            for (int nd2 = 0; nd2 < 4; ++nd2) {
                const uint4 f = bV[(kp * 4 + nd2) * 32 + lane];
                mma_f16(o[0][2 * nd2], a0, f.x, f.y);
                mma_f16(o[0][2 * nd2 + 1], a0, f.z, f.w);
                mma_f16(o[1][2 * nd2], a1, f.x, f.y);
                mma_f16(o[1][2 * nd2 + 1], a1, f.z, f.w);
            }
        }
        __syncthreads();
    }

    // ---- epilogue per query half: normalize + write fp16 A-pack quads ----
#pragma unroll
    for (int hf = 0; hf < 2; ++hf) {
        const float inv0 = 1.0f / lacc[hf][0];
        const float inv1 = 1.0f / lacc[hf][2];
#pragma unroll
        for (int sd = 0; sd < 4; ++sd) {
            uint4 w;
            w.x = packf16(o[hf][2 * sd][0] * inv0,     o[hf][2 * sd][1] * inv0);
            w.y = packf16(o[hf][2 * sd][2] * inv1,     o[hf][2 * sd][3] * inv1);
            w.z = packf16(o[hf][2 * sd + 1][0] * inv0, o[hf][2 * sd + 1][1] * inv0);
            w.w = packf16(o[hf][2 * sd + 1][2] * inv1, o[hf][2 * sd + 1][3] * inv1);
            Opacked[((size_t)(R0 + hf) * 64 + h * 4 + sd) * 32 + lane] = w;
        }
    }
}

// ===========================================================================
extern "C" void kernel_launch(void* const* d_in, const int* in_sizes, int n_in,
                              void* d_out, int out_size)
{
    const float* x     = (const float*)d_in[0];
    const float* eng   = (const float*)d_in[1];
    const void*  mask  = (const void*)d_in[2];
    const float* qkv_w = (const float*)d_in[3];
    const float* qkv_b = (const float*)d_in[4];
    const float* out_w = (const float*)d_in[5];
    const float* out_b = (const float*)d_in[6];
    float* out = (float*)d_out;

    uint4 *qp = nullptr, *kq = nullptr, *vq = nullptr;
    uint4 *xp = nullptr, *op = nullptr, *wq = nullptr, *wo = nullptr;
    cudaGetSymbolAddress((void**)&qp, g_qp);
    cudaGetSymbolAddress((void**)&kq, g_Kq);
    cudaGetSymbolAddress((void**)&vq, g_Vq);
    cudaGetSymbolAddress((void**)&xp, g_xp);
    cudaGetSymbolAddress((void**)&op, g_op);
    cudaGetSymbolAddress((void**)&wq, g_wq);
    cudaGetSymbolAddress((void**)&wo, g_wo);

    cudaFuncSetAttribute(f16_gemm_packed,
                         cudaFuncAttributeMaxDynamicSharedMemorySize, GP_SMEM_BYTES);
    cudaFuncSetAttribute(qkv_gemm_fused,
                         cudaFuncAttributeMaxDynamicSharedMemorySize, GP_SMEM_BYTES);
    cudaFuncSetAttribute(attn_kernel,
                         cudaFuncAttributeMaxDynamicSharedMemorySize, ATTN_SMEM_BYTES);

    // 0) mask dtype detection + per-key bias precompute (log2 domain)
    detect_mask_kernel<<<1, 256>>>((const unsigned char*)mask);
    bias_kernel<<<(Bb * Ts + 255) / 256, 256>>>(eng, mask);

    // 0b) pack x and weights into fp16 fragment layouts
    pack_a_f16<<<2048, 256>>>(x, xp, M_ROWS, Dd);
    pack_b_f16<<<1536, 256>>>(qkv_w, wq, QKV_N, Dd);
    pack_b_f16<<<512, 256>>>(out_w, wo, Dd, Dd);

    // 1) fused QKV projection -> Q A-pack, K B-pack, V frag tiles
    dim3 g1(QKV_N / 128, M_ROWS / 128);
    qkv_gemm_fused<<<g1, 256, GP_SMEM_BYTES>>>(xp, wq, qkv_b, qp, kq, vq);

    // 2) attention: 128 queries / CTA, 32 per warp -> halved smem traffic
    dim3 g2(Ts / 128, Hh, Bb);
    attn_kernel<<<g2, 128, ATTN_SMEM_BYTES>>>(qp, op);

    // 3) output projection (packed fp16 mma.sync, 4-stage pipeline)
    dim3 g3(Dd / 128, M_ROWS / 128);
    f16_gemm_packed<<<g3, 256, GP_SMEM_BYTES>>>(op, wo, out_b, out, Dd, Dd);
}

// round 15
// speedup vs baseline: 1.1323x; 1.0807x over previous
#include <cuda_runtime.h>
#include <cuda_bf16.h>
#include <cuda_fp16.h>
#include <math.h>
#include <stdint.h>

// Problem constants
#define Bb 4
#define Ts 2048
#define Dd 1024
#define Hh 16
#define HD 64
#define M_ROWS 8192
#define QKV_N 3072

// Scratch (device globals: allocation-free)
__device__ float g_bias[Bb * Ts];                 // per-key log2-domain bias
__device__ int   g_maskMode;
// Fragment-ready fp16 buffers
__device__ uint4 g_qp[(size_t)(M_ROWS / 16) * 64 * 32];   // Q A-pack
__device__ uint4 g_Kq[(size_t)Bb * Hh * 32 * 512];        // K B-pack tiles
__device__ uint4 g_Vq[(size_t)Bb * Hh * 32 * 512];        // V frag tiles
__device__ uint4 g_xp[(size_t)(M_ROWS / 16) * 64 * 32];   // x A-pack
__device__ uint4 g_op[(size_t)(M_ROWS / 16) * 64 * 32];   // attn-out A-pack
__device__ uint4 g_wq[(size_t)(QKV_N / 8) * 32 * 32];     // qkv_w B-pack
__device__ uint4 g_wo[(size_t)(Dd / 8) * 32 * 32];        // out_w B-pack

// ===========================================================================
// helpers
// ===========================================================================
__device__ __forceinline__ uint32_t packf16(float lo, float hi) {
    uint32_t r;
    asm("cvt.rn.f16x2.f32 %0, %1, %2;" : "=r"(r) : "f"(hi), "f"(lo));
    return r;
}
__device__ __forceinline__ uint32_t ex2_f16x2(uint32_t x) {
    uint32_t r;
    asm("ex2.approx.f16x2 %0, %1;" : "=r"(r) : "r"(x));
    return r;
}

__device__ __forceinline__ void mma_f16(float* c, const uint32_t* a, uint32_t b0, uint32_t b1) {
    asm volatile(
        "mma.sync.aligned.m16n8k16.row.col.f32.f16.f16.f32 "
        "{%0,%1,%2,%3}, {%4,%5,%6,%7}, {%8,%9}, {%0,%1,%2,%3};\n"
        : "+f"(c[0]), "+f"(c[1]), "+f"(c[2]), "+f"(c[3])
        : "r"(a[0]), "r"(a[1]), "r"(a[2]), "r"(a[3]), "r"(b0), "r"(b1));
}
__device__ __forceinline__ void mma_f16q(float* c, const uint4& a, uint32_t b0, uint32_t b1) {
    asm volatile(
        "mma.sync.aligned.m16n8k16.row.col.f32.f16.f16.f32 "
        "{%0,%1,%2,%3}, {%4,%5,%6,%7}, {%8,%9}, {%0,%1,%2,%3};\n"
        : "+f"(c[0]), "+f"(c[1]), "+f"(c[2]), "+f"(c[3])
        : "r"(a.x), "r"(a.y), "r"(a.z), "r"(a.w), "r"(b0), "r"(b1));
}

__device__ __forceinline__ uint32_t smem_u32(const void* p) {
    uint32_t a;
    asm("{ .reg .u64 t; cvta.to.shared.u64 t, %1; cvt.u32.u64 %0, t; }" : "=r"(a) : "l"(p));
    return a;
}
__device__ __forceinline__ void cp_async16(uint32_t dst, const void* src) {
    asm volatile("cp.async.cg.shared.global [%0], [%1], 16;" :: "r"(dst), "l"(src));
}
#define CP_COMMIT() asm volatile("cp.async.commit_group;" ::: "memory")
#define CP_WAIT(n)  asm volatile("cp.async.wait_group %0;" :: "n"(n) : "memory")

// ===========================================================================
// Mask dtype detection + bias precompute (log2 domain)
// ===========================================================================
__global__ void detect_mask_kernel(const unsigned char* __restrict__ mask)
{
    __shared__ unsigned int orr[4][256];
    const int tid = threadIdx.x;
    unsigned int o0 = 0, o1 = 0, o2 = 0, o3 = 0;
    for (int i = tid * 4; i < Bb * Ts; i += 256 * 4) {
        o0 |= mask[i + 0]; o1 |= mask[i + 1]; o2 |= mask[i + 2]; o3 |= mask[i + 3];
    }
    orr[0][tid] = o0; orr[1][tid] = o1; orr[2][tid] = o2; orr[3][tid] = o3;
    __syncthreads();
    for (int s = 128; s; s >>= 1) {
        if (tid < s) {
            orr[0][tid] |= orr[0][tid + s];
            orr[1][tid] |= orr[1][tid + s];
            orr[2][tid] |= orr[2][tid + s];
            orr[3][tid] |= orr[3][tid + s];
        }
        __syncthreads();
    }
    if (tid == 0) {
        unsigned int l0 = orr[0][0], l1 = orr[1][0], l2 = orr[2][0], l3 = orr[3][0];
        int mode;
        if ((l1 | l2 | l3) == 0u) mode = 1;
        else if ((l0 | l1) == 0u && (l2 | l3) != 0u) mode = 2;
        else mode = 0;
        g_maskMode = mode;
    }
}

__global__ void bias_kernel(const float* __restrict__ eng, const void* __restrict__ mask)
{
    const int kk = blockIdx.x * 256 + threadIdx.x;
    if (kk >= Bb * Ts) return;
    const int mode = g_maskMode;
    bool m;
    if (mode == 1)      m = ((const int*)mask)[kk] != 0;
    else if (mode == 2) m = ((const float*)mask)[kk] != 0.f;
    else                m = ((const unsigned char*)mask)[kk] != 0;
    g_bias[kk] = m ? -1e9f : log2f(fmaxf(eng[kk], 1e-6f));
}

// ===========================================================================
// fp16 fragment packing (A- and B-layouts)
// ===========================================================================
__global__ void __launch_bounds__(256)
pack_a_f16(const float* __restrict__ src, uint4* __restrict__ dst, int M, int K)
{
    const int K16 = K >> 4;
    const int total = (M >> 4) * K16 * 32;
    for (int q = blockIdx.x * 256 + threadIdx.x; q < total; q += gridDim.x * 256) {
        const int lane = q & 31;
        const int rs = q >> 5;
        const int S = rs % K16;
        const int R = rs / K16;
        const int g = lane >> 2, t = lane & 3;
        const float* p = src + (size_t)(R * 16 + g) * K + S * 16 + 2 * t;
        const float* p2 = p + (size_t)8 * K;
        const float2 a0 = *(const float2*)(p);
        const float2 a1 = *(const float2*)(p2);
        const float2 a2 = *(const float2*)(p + 8);
        const float2 a3 = *(const float2*)(p2 + 8);
        uint4 w;
        w.x = packf16(a0.x, a0.y);
        w.y = packf16(a1.x, a1.y);
        w.z = packf16(a2.x, a2.y);
        w.w = packf16(a3.x, a3.y);
        dst[q] = w;
    }
}

__global__ void __launch_bounds__(256)
pack_b_f16(const float* __restrict__ src, uint4* __restrict__ dst, int N, int K)
{
    const int K32 = K >> 5;
    const int total = (N >> 3) * K32 * 32;
    for (int q = blockIdx.x * 256 + threadIdx.x; q < total; q += gridDim.x * 256) {
        const int lane = q & 31;
        const int cs = q >> 5;
        const int S = cs % K32;
        const int C = cs / K32;
        const int g = lane >> 2, t = lane & 3;
        const float* p = src + (size_t)(C * 8 + g) * K + S * 32 + 2 * t;
        const float2 b0 = *(const float2*)(p);
        const float2 b1 = *(const float2*)(p + 8);
        const float2 b2 = *(const float2*)(p + 16);
        const float2 b3 = *(const float2*)(p + 24);
        uint4 w;
        w.x = packf16(b0.x, b0.y);
        w.y = packf16(b1.x, b1.y);
        w.z = packf16(b2.x, b2.y);
        w.w = packf16(b3.x, b3.y);
        dst[q] = w;
    }
}

// ===========================================================================
// GEMM: 128x128 CTA tile, 4 warps x 64x64 warp tiles, BK=32, 4-stage cp.async.
// Crossbar: 64 LDS.128/chunk (vs 96 with 8x 32x64 warps).
// ===========================================================================
#define GP_SMEM_BYTES 65536

__global__ void __launch_bounds__(128, 2)
f16_gemm_packed(const uint4* __restrict__ Ap, const uint4* __restrict__ Bp,
                const float* __restrict__ bias, float* __restrict__ C,
                int K, int ldc)
{
    extern __shared__ uint4 ps[];
    uint4* sA = ps;            // [4][512]
    uint4* sB = ps + 2048;     // [4][512]
    const uint32_t sAaddr = smem_u32(sA);
    const uint32_t sBaddr = smem_u32(sB);

    const int tid  = threadIdx.x;
    const int wid  = tid >> 5;       // 0..3
    const int lane = tid & 31;
    const int g = lane >> 2, t = lane & 3;
    const int wm = wid & 1;          // M half (64 rows)
    const int wn = wid >> 1;         // N half (64 cols)
    const int bm = blockIdx.y * 128;
    const int bn = blockIdx.x * 128;
    const int K16 = K >> 4;
    const int K32 = K >> 5;
    const int Rb = bm >> 4;
    const int Cb = bn >> 3;

    float acc[4][8][4];
#pragma unroll
    for (int mi = 0; mi < 4; ++mi)
#pragma unroll
        for (int ni = 0; ni < 8; ++ni)
#pragma unroll
            for (int r = 0; r < 4; ++r) acc[mi][ni][r] = 0.f;

    auto issue = [&](int buf, int kt) {
#pragma unroll
        for (int i = 0; i < 4; ++i) {
            const int l    = tid + 128 * i;   // 0..511
            const int tile = l >> 5;          // 0..15
            const int ln   = l & 31;
            cp_async16(sAaddr + buf * 8192 + l * 16,
                       Ap + ((size_t)(Rb + (tile >> 1)) * K16 + 2 * kt + (tile & 1)) * 32 + ln);
            cp_async16(sBaddr + buf * 8192 + l * 16,
                       Bp + ((size_t)(Cb + tile) * K32 + kt) * 32 + ln);
        }
    };

    const int nChunks = K >> 5;
#pragma unroll
    for (int p = 0; p < 3; ++p) {
        if (p < nChunks) { issue(p, p); CP_COMMIT(); }
    }

    for (int kt = 0; kt < nChunks; ++kt) {
        if (kt + 3 < nChunks) {
            issue((kt + 3) & 3, kt + 3);
            CP_COMMIT();
            CP_WAIT(3);
        } else if (kt + 2 < nChunks) { CP_WAIT(2); }
        else if (kt + 1 < nChunks)   { CP_WAIT(1); }
        else                         { CP_WAIT(0); }
        __syncthreads();

        const uint4* bufA = sA + (kt & 3) * 512;
        const uint4* bufB = sB + (kt & 3) * 512;
        uint4 fa[4][2];
#pragma unroll
        for (int mi = 0; mi < 4; ++mi)
#pragma unroll
            for (int kc = 0; kc < 2; ++kc)
                fa[mi][kc] = bufA[(((wm * 4 + mi) << 1) | kc) * 32 + lane];
#pragma unroll
        for (int ni = 0; ni < 8; ++ni) {
            const uint4 f = bufB[(wn * 8 + ni) * 32 + lane];
#pragma unroll
            for (int mi = 0; mi < 4; ++mi) {
                mma_f16q(acc[mi][ni], fa[mi][0], f.x, f.y);
                mma_f16q(acc[mi][ni], fa[mi][1], f.z, f.w);
            }
        }
        __syncthreads();
    }

#pragma unroll
    for (int mi = 0; mi < 4; ++mi) {
        const int row = bm + wm * 64 + mi * 16 + g;
#pragma unroll
        for (int ni = 0; ni < 8; ++ni) {
            const int col = bn + wn * 64 + ni * 8 + 2 * t;
            const float b0 = bias[col];
            const float b1 = bias[col + 1];
            float2 lo, hi;
            lo.x = acc[mi][ni][0] + b0; lo.y = acc[mi][ni][1] + b1;
            hi.x = acc[mi][ni][2] + b0; hi.y = acc[mi][ni][3] + b1;
            *(float2*)(C + (size_t)row * ldc + col) = lo;
            *(float2*)(C + (size_t)(row + 8) * ldc + col) = hi;
        }
    }
}

// ===========================================================================
// Fused QKV GEMM: 4 warps x 64x64, epilogues re-indexed for 2x2 warp grid.
// grid.x = 24 col-blocks: 0-7 Q, 8-15 K, 16-23 V.
// ===========================================================================
__global__ void __launch_bounds__(128, 2)
qkv_gemm_fused(const uint4* __restrict__ Ap, const uint4* __restrict__ Bp,
               const float* __restrict__ bias,
               uint4* __restrict__ Qp, uint4* __restrict__ Kq, uint4* __restrict__ Vq)
{
    extern __shared__ uint4 ps[];
    uint4* sA = ps;
    uint4* sB = ps + 2048;
    const uint32_t sAaddr = smem_u32(sA);
    const uint32_t sBaddr = smem_u32(sB);

    const int tid  = threadIdx.x;
    const int wid  = tid >> 5;
    const int lane = tid & 31;
    const int g = lane >> 2, t = lane & 3;
    const int wm = wid & 1;
    const int wn = wid >> 1;
    const int bm = blockIdx.y * 128;
    const int bn = blockIdx.x * 128;
    const int K16 = Dd >> 4;
    const int K32 = Dd >> 5;
    const int Rb = bm >> 4;
    const int Cb = bn >> 3;

    float acc[4][8][4];
#pragma unroll
    for (int mi = 0; mi < 4; ++mi)
#pragma unroll
        for (int ni = 0; ni < 8; ++ni)
#pragma unroll
            for (int r = 0; r < 4; ++r) acc[mi][ni][r] = 0.f;

    auto issue = [&](int buf, int kt) {
#pragma unroll
        for (int i = 0; i < 4; ++i) {
            const int l    = tid + 128 * i;
            const int tile = l >> 5;
            const int ln   = l & 31;
            cp_async16(sAaddr + buf * 8192 + l * 16,
                       Ap + ((size_t)(Rb + (tile >> 1)) * K16 + 2 * kt + (tile & 1)) * 32 + ln);
            cp_async16(sBaddr + buf * 8192 + l * 16,
                       Bp + ((size_t)(Cb + tile) * K32 + kt) * 32 + ln);
        }
    };

    const int nChunks = Dd >> 5;
#pragma unroll
    for (int p = 0; p < 3; ++p) { issue(p, p); CP_COMMIT(); }

    for (int kt = 0; kt < nChunks; ++kt) {
        if (kt + 3 < nChunks) {
            issue((kt + 3) & 3, kt + 3);
            CP_COMMIT();
            CP_WAIT(3);
        } else if (kt + 2 < nChunks) { CP_WAIT(2); }
        else if (kt + 1 < nChunks)   { CP_WAIT(1); }
        else                         { CP_WAIT(0); }
        __syncthreads();

        const uint4* bufA = sA + (kt & 3) * 512;
        const uint4* bufB = sB + (kt & 3) * 512;
        uint4 fa[4][2];
#pragma unroll
        for (int mi = 0; mi < 4; ++mi)
#pragma unroll
            for (int kc = 0; kc < 2; ++kc)
                fa[mi][kc] = bufA[(((wm * 4 + mi) << 1) | kc) * 32 + lane];
#pragma unroll
        for (int ni = 0; ni < 8; ++ni) {
            const uint4 f = bufB[(wn * 8 + ni) * 32 + lane];
#pragma unroll
            for (int mi = 0; mi < 4; ++mi) {
                mma_f16q(acc[mi][ni], fa[mi][0], f.x, f.y);
                mma_f16q(acc[mi][ni], fa[mi][1], f.z, f.w);
            }
        }
        __syncthreads();
    }

    const int region = blockIdx.x >> 3;

    if (region == 0) {
        // ---- Q: emit A-pack quads directly ----
#pragma unroll
        for (int mi = 0; mi < 4; ++mi) {
            const int R = Rb + wm * 4 + mi;
#pragma unroll
            for (int s = 0; s < 4; ++s) {
                const int colb = bn + wn * 64 + s * 16;
                const float b0 = bias[colb + 2 * t];
                const float b1 = bias[colb + 2 * t + 1];
                const float b2 = bias[colb + 8 + 2 * t];
                const float b3 = bias[colb + 8 + 2 * t + 1];
                uint4 w;
                w.x = packf16(acc[mi][2 * s][0] + b0,     acc[mi][2 * s][1] + b1);
                w.y = packf16(acc[mi][2 * s][2] + b0,     acc[mi][2 * s][3] + b1);
                w.z = packf16(acc[mi][2 * s + 1][0] + b2, acc[mi][2 * s + 1][1] + b3);
                w.w = packf16(acc[mi][2 * s + 1][2] + b2, acc[mi][2 * s + 1][3] + b3);
                const int Scol = blockIdx.x * 8 + wn * 4 + s;
                Qp[((size_t)R * 64 + Scol) * 32 + lane] = w;
            }
        }
    } else if (region == 1) {
        // ---- K: emit B-pack quads directly ----
        const int h = (blockIdx.x - 8) * 2 + wn;
#pragma unroll
        for (int mi = 0; mi < 4; ++mi) {
            const int rowbase = bm + wm * 64 + mi * 16;
            const int bb  = rowbase >> 11;
            const int tok = rowbase & 2047;
            const int kt  = tok >> 6;
            const int nt0 = (tok >> 3) & 7;
            const size_t base = ((size_t)(bb * Hh + h) * 32 + kt) * 512;
#pragma unroll
            for (int ksp = 0; ksp < 2; ++ksp) {
                const int colb = bn + wn * 64 + 32 * ksp;
                float bb0[4], bb1[4];
#pragma unroll
                for (int j = 0; j < 4; ++j) {
                    bb0[j] = bias[colb + 8 * j + 2 * t];
                    bb1[j] = bias[colb + 8 * j + 2 * t + 1];
                }
                uint4 w0, w1;
                w0.x = packf16(acc[mi][4 * ksp + 0][0] + bb0[0], acc[mi][4 * ksp + 0][1] + bb1[0]);
                w0.y = packf16(acc[mi][4 * ksp + 1][0] + bb0[1], acc[mi][4 * ksp + 1][1] + bb1[1]);
                w0.z = packf16(acc[mi][4 * ksp + 2][0] + bb0[2], acc[mi][4 * ksp + 2][1] + bb1[2]);
                w0.w = packf16(acc[mi][4 * ksp + 3][0] + bb0[3], acc[mi][4 * ksp + 3][1] + bb1[3]);
                w1.x = packf16(acc[mi][4 * ksp + 0][2] + bb0[0], acc[mi][4 * ksp + 0][3] + bb1[0]);
                w1.y = packf16(acc[mi][4 * ksp + 1][2] + bb0[1], acc[mi][4 * ksp + 1][3] + bb1[1]);
                w1.z = packf16(acc[mi][4 * ksp + 2][2] + bb0[2], acc[mi][4 * ksp + 2][3] + bb1[2]);
                w1.w = packf16(acc[mi][4 * ksp + 3][2] + bb0[3], acc[mi][4 * ksp + 3][3] + bb1[3]);
                Kq[base + ((size_t)(nt0 * 2 + ksp)) * 32 + lane] = w0;
                Kq[base + ((size_t)((nt0 + 1) * 2 + ksp)) * 32 + lane] = w1;
            }
        }
    } else {
        // ---- V: smem transpose (stride 136 halves), emit quads ----
        unsigned short* sT = (unsigned short*)ps;   // 128 x 136 halves = 34.8KB
#pragma unroll
        for (int mi = 0; mi < 4; ++mi) {
            const int r0 = wm * 64 + mi * 16 + g;
#pragma unroll
            for (int ni = 0; ni < 8; ++ni) {
                const int c = wn * 64 + ni * 8 + 2 * t;
                const float b0 = bias[bn + c];
                const float b1 = bias[bn + c + 1];
                *(uint32_t*)&sT[r0 * 136 + c]       = packf16(acc[mi][ni][0] + b0, acc[mi][ni][1] + b1);
                *(uint32_t*)&sT[(r0 + 8) * 136 + c] = packf16(acc[mi][ni][2] + b0, acc[mi][ni][3] + b1);
            }
        }
        __syncthreads();

        const int bb   = bm >> 11;
        const int tokb = bm & 2047;
#pragma unroll
        for (int i = 0; i < 16; ++i) {
            const int q6   = i * 4 + (tid >> 5);   // 0..63
            const int head = q6 >> 5;
            const int kt2  = (q6 >> 4) & 1;
            const int kp   = (q6 >> 2) & 3;
            const int nd2  = q6 & 3;
            const int r0 = kt2 * 64 + kp * 16 + 2 * t;
            const int c0 = head * 64 + nd2 * 16 + g;
            uint4 w;
            w.x = (uint32_t)sT[r0 * 136 + c0]           | ((uint32_t)sT[(r0 + 1) * 136 + c0] << 16);
            w.y = (uint32_t)sT[(r0 + 8) * 136 + c0]     | ((uint32_t)sT[(r0 + 9) * 136 + c0] << 16);
            w.z = (uint32_t)sT[r0 * 136 + c0 + 8]       | ((uint32_t)sT[(r0 + 1) * 136 + c0 + 8] << 16);
            w.w = (uint32_t)sT[(r0 + 8) * 136 + c0 + 8] | ((uint32_t)sT[(r0 + 9) * 136 + c0 + 8] << 16);
            const int hg  = (blockIdx.x - 16) * 2 + head;
            const int ktg = (tokb >> 6) + kt2;
            Vq[((size_t)(bb * Hh + hg) * 32 + ktg) * 512 + (kp * 4 + nd2) * 32 + lane] = w;
        }
    }
}

// ===========================================================================
// Flash attention (round 14, unchanged): 32 queries/warp, 128 q / 128-thread
// CTA, 2-stage cp.async, ex2.f16x2 softmax, ones-B MMA row sums.
// ===========================================================================
#define ATTN_SMEM_BYTES (2 * 8192 + 2 * 8192 + 2 * 256)
#define C1 0.18033688011112042f   // 0.125 * log2(e)
#define ONESF16X2 0x3C003C00u     // (1.0h, 1.0h)

__global__ void __launch_bounds__(128, 2)
attn_kernel(const uint4* __restrict__ Qp, uint4* __restrict__ Opacked)
{
    extern __shared__ uint4 asm4[];
    uint4* sK = asm4;                      // [2][512]
    uint4* sV = asm4 + 1024;               // [2][512]
    float* sBias = (float*)(asm4 + 2048);  // [2][64]

    const uint32_t sKaddr = smem_u32(sK);
    const uint32_t sVaddr = smem_u32(sV);
    const uint32_t sBaddr = smem_u32(sBias);

    const int qt = blockIdx.x;
    const int h  = blockIdx.y;
    const int b  = blockIdx.z;
    const int tid  = threadIdx.x;
    const int warp = tid >> 5;
    const int lane = tid & 31;
    const int t = lane & 3;

    const size_t kvBase = ((size_t)(b * Hh + h)) * 32 * 512;
    const int R0 = (b * Ts + qt * 128 + warp * 32) >> 4;

    uint4 qf[2][4];
#pragma unroll
    for (int hf = 0; hf < 2; ++hf)
#pragma unroll
        for (int ks = 0; ks < 4; ++ks)
            qf[hf][ks] = Qp[((size_t)(R0 + hf) * 64 + h * 4 + ks) * 32 + lane];

    float o[2][8][4];
#pragma unroll
    for (int hf = 0; hf < 2; ++hf)
#pragma unroll
        for (int i = 0; i < 8; ++i)
#pragma unroll
            for (int j = 0; j < 4; ++j) o[hf][i][j] = 0.f;
    float lacc[2][4] = {{0.f, 0.f, 0.f, 0.f}, {0.f, 0.f, 0.f, 0.f}};

    auto issue = [&](int buf, int kt) {
        const uint4* srcK = g_Kq + kvBase + (size_t)kt * 512 + tid;
        const uint4* srcV = g_Vq + kvBase + (size_t)kt * 512 + tid;
        const uint32_t dK = sKaddr + buf * 8192 + tid * 16;
        const uint32_t dV = sVaddr + buf * 8192 + tid * 16;
#pragma unroll
        for (int i = 0; i < 4; ++i) {
            cp_async16(dK + i * 2048, srcK + i * 128);
            cp_async16(dV + i * 2048, srcV + i * 128);
        }
        if (tid < 16) cp_async16(sBaddr + buf * 256 + tid * 16, g_bias + b * Ts + kt * 64 + tid * 4);
    };

    issue(0, 0);
    CP_COMMIT();

    for (int kt = 0; kt < Ts / 64; ++kt) {
        const int buf = kt & 1;
        if (kt + 1 < Ts / 64) {
            issue(buf ^ 1, kt + 1);
            CP_COMMIT();
            CP_WAIT(1);
        } else {
            CP_WAIT(0);
        }
        __syncthreads();

        const uint4* bK = sK + buf * 512;
        const uint4* bV = sV + buf * 512;
        const float* bB = sBias + buf * 64;

        float sacc[2][8][4];
#pragma unroll
        for (int hf = 0; hf < 2; ++hf)
#pragma unroll
            for (int nt = 0; nt < 8; ++nt)
#pragma unroll
                for (int j = 0; j < 4; ++j) sacc[hf][nt][j] = 0.f;
#pragma unroll
        for (int ksp = 0; ksp < 2; ++ksp) {
#pragma unroll
            for (int nt = 0; nt < 8; ++nt) {
                const uint4 f = bK[(nt * 2 + ksp) * 32 + lane];
                mma_f16q(sacc[0][nt], qf[0][2 * ksp], f.x, f.y);
                mma_f16q(sacc[0][nt], qf[0][2 * ksp + 1], f.z, f.w);
                mma_f16q(sacc[1][nt], qf[1][2 * ksp], f.x, f.y);
                mma_f16q(sacc[1][nt], qf[1][2 * ksp + 1], f.z, f.w);
            }
        }

        uint32_t ph[2][8][2];
#pragma unroll
        for (int nt = 0; nt < 8; ++nt) {
            const float2 bb2 = *(const float2*)(bB + 8 * nt + 2 * t);
#pragma unroll
            for (int hf = 0; hf < 2; ++hf) {
                const float a0 = fmaf(sacc[hf][nt][0], C1, bb2.x);
                const float a1 = fmaf(sacc[hf][nt][1], C1, bb2.y);
                const float a2 = fmaf(sacc[hf][nt][2], C1, bb2.x);
                const float a3 = fmaf(sacc[hf][nt][3], C1, bb2.y);
                ph[hf][nt][0] = ex2_f16x2(packf16(a0, a1));
                ph[hf][nt][1] = ex2_f16x2(packf16(a2, a3));
            }
        }

#pragma unroll
        for (int kp = 0; kp < 4; ++kp) {
            const uint32_t a0[4] = { ph[0][2 * kp][0], ph[0][2 * kp][1],
                                     ph[0][2 * kp + 1][0], ph[0][2 * kp + 1][1] };
            const uint32_t a1[4] = { ph[1][2 * kp][0], ph[1][2 * kp][1],
                                     ph[1][2 * kp + 1][0], ph[1][2 * kp + 1][1] };
            mma_f16(lacc[0], a0, ONESF16X2, ONESF16X2);
            mma_f16(lacc[1], a1, ONESF16X2, ONESF16X2);
#pragma unroll
            for (int nd2 = 0; nd2 < 4; ++nd2) {
                const uint4 f = bV[(kp * 4 + nd2) * 32 + lane];
                mma_f16(o[0][2 * nd2], a0, f.x, f.y);
                mma_f16(o[0][2 * nd2 + 1], a0, f.z, f.w);
                mma_f16(o[1][2 * nd2], a1, f.x, f.y);
                mma_f16(o[1][2 * nd2 + 1], a1, f.z, f.w);
            }
        }
        __syncthreads();
    }

#pragma unroll
    for (int hf = 0; hf < 2; ++hf) {
        const float inv0 = 1.0f / lacc[hf][0];
        const float inv1 = 1.0f / lacc[hf][2];
#pragma unroll
        for (int sd = 0; sd < 4; ++sd) {
            uint4 w;
            w.x = packf16(o[hf][2 * sd][0] * inv0,     o[hf][2 * sd][1] * inv0);
            w.y = packf16(o[hf][2 * sd][2] * inv1,     o[hf][2 * sd][3] * inv1);
            w.z = packf16(o[hf][2 * sd + 1][0] * inv0, o[hf][2 * sd + 1][1] * inv0);
            w.w = packf16(o[hf][2 * sd + 1][2] * inv1, o[hf][2 * sd + 1][3] * inv1);
            Opacked[((size_t)(R0 + hf) * 64 + h * 4 + sd) * 32 + lane] = w;
        }
    }
}

// ===========================================================================
extern "C" void kernel_launch(void* const* d_in, const int* in_sizes, int n_in,
                              void* d_out, int out_size)
{
    const float* x     = (const float*)d_in[0];
    const float* eng   = (const float*)d_in[1];
    const void*  mask  = (const void*)d_in[2];
    const float* qkv_w = (const float*)d_in[3];
    const float* qkv_b = (const float*)d_in[4];
    const float* out_w = (const float*)d_in[5];
    const float* out_b = (const float*)d_in[6];
    float* out = (float*)d_out;

    uint4 *qp = nullptr, *kq = nullptr, *vq = nullptr;
    uint4 *xp = nullptr, *op = nullptr, *wq = nullptr, *wo = nullptr;
    cudaGetSymbolAddress((void**)&qp, g_qp);
    cudaGetSymbolAddress((void**)&kq, g_Kq);
    cudaGetSymbolAddress((void**)&vq, g_Vq);
    cudaGetSymbolAddress((void**)&xp, g_xp);
    cudaGetSymbolAddress((void**)&op, g_op);
    cudaGetSymbolAddress((void**)&wq, g_wq);
    cudaGetSymbolAddress((void**)&wo, g_wo);

    cudaFuncSetAttribute(f16_gemm_packed,
                         cudaFuncAttributeMaxDynamicSharedMemorySize, GP_SMEM_BYTES);
    cudaFuncSetAttribute(qkv_gemm_fused,
                         cudaFuncAttributeMaxDynamicSharedMemorySize, GP_SMEM_BYTES);
    cudaFuncSetAttribute(attn_kernel,
                         cudaFuncAttributeMaxDynamicSharedMemorySize, ATTN_SMEM_BYTES);

    // 0) mask dtype detection + per-key bias precompute (log2 domain)
    detect_mask_kernel<<<1, 256>>>((const unsigned char*)mask);
    bias_kernel<<<(Bb * Ts + 255) / 256, 256>>>(eng, mask);

    // 0b) pack x and weights into fp16 fragment layouts
    pack_a_f16<<<2048, 256>>>(x, xp, M_ROWS, Dd);
    pack_b_f16<<<1536, 256>>>(qkv_w, wq, QKV_N, Dd);
    pack_b_f16<<<512, 256>>>(out_w, wo, Dd, Dd);

    // 1) fused QKV projection -> Q A-pack, K B-pack, V frag tiles
    dim3 g1(QKV_N / 128, M_ROWS / 128);
    qkv_gemm_fused<<<g1, 128, GP_SMEM_BYTES>>>(xp, wq, qkv_b, qp, kq, vq);

    // 2) attention: 128 queries / CTA, 32 per warp
    dim3 g2(Ts / 128, Hh, Bb);
    attn_kernel<<<g2, 128, ATTN_SMEM_BYTES>>>(qp, op);

    // 3) output projection (4 warps x 64x64, 4-stage pipeline)
    dim3 g3(Dd / 128, M_ROWS / 128);
    f16_gemm_packed<<<g3, 128, GP_SMEM_BYTES>>>(op, wo, out_b, out, Dd, Dd);
}

// round 16
// speedup vs baseline: 1.1439x; 1.0103x over previous
#include <cuda_runtime.h>
#include <cuda_bf16.h>
#include <cuda_fp16.h>
#include <math.h>
#include <stdint.h>

// Problem constants
#define Bb 4
#define Ts 2048
#define Dd 1024
#define Hh 16
#define HD 64
#define M_ROWS 8192
#define QKV_N 3072

// Scratch (device globals: allocation-free)
__device__ float g_bias[Bb * Ts];                 // per-key log2-domain bias
__device__ int   g_maskMode;
// Fragment-ready fp16 buffers
__device__ uint4 g_qp[(size_t)(M_ROWS / 16) * 64 * 32];   // Q A-pack
__device__ uint4 g_Kq[(size_t)Bb * Hh * 32 * 512];        // K B-pack tiles
__device__ uint4 g_Vq[(size_t)Bb * Hh * 32 * 512];        // V frag tiles
__device__ uint4 g_xp[(size_t)(M_ROWS / 16) * 64 * 32];   // x A-pack
__device__ uint4 g_op[(size_t)(M_ROWS / 16) * 64 * 32];   // attn-out A-pack
__device__ uint4 g_wq[(size_t)(QKV_N / 8) * 32 * 32];     // qkv_w B-pack
__device__ uint4 g_wo[(size_t)(Dd / 8) * 32 * 32];        // out_w B-pack

// ===========================================================================
// helpers
// ===========================================================================
__device__ __forceinline__ uint32_t packf16(float lo, float hi) {
    uint32_t r;
    asm("cvt.rn.f16x2.f32 %0, %1, %2;" : "=r"(r) : "f"(hi), "f"(lo));
    return r;
}
__device__ __forceinline__ uint32_t ex2_f16x2(uint32_t x) {
    uint32_t r;
    asm("ex2.approx.f16x2 %0, %1;" : "=r"(r) : "r"(x));
    return r;
}

__device__ __forceinline__ void mma_f16(float* c, const uint32_t* a, uint32_t b0, uint32_t b1) {
    asm volatile(
        "mma.sync.aligned.m16n8k16.row.col.f32.f16.f16.f32 "
        "{%0,%1,%2,%3}, {%4,%5,%6,%7}, {%8,%9}, {%0,%1,%2,%3};\n"
        : "+f"(c[0]), "+f"(c[1]), "+f"(c[2]), "+f"(c[3])
        : "r"(a[0]), "r"(a[1]), "r"(a[2]), "r"(a[3]), "r"(b0), "r"(b1));
}
__device__ __forceinline__ void mma_f16q(float* c, const uint4& a, uint32_t b0, uint32_t b1) {
    asm volatile(
        "mma.sync.aligned.m16n8k16.row.col.f32.f16.f16.f32 "
        "{%0,%1,%2,%3}, {%4,%5,%6,%7}, {%8,%9}, {%0,%1,%2,%3};\n"
        : "+f"(c[0]), "+f"(c[1]), "+f"(c[2]), "+f"(c[3])
        : "r"(a.x), "r"(a.y), "r"(a.z), "r"(a.w), "r"(b0), "r"(b1));
}

__device__ __forceinline__ uint32_t smem_u32(const void* p) {
    uint32_t a;
    asm("{ .reg .u64 t; cvta.to.shared.u64 t, %1; cvt.u32.u64 %0, t; }" : "=r"(a) : "l"(p));
    return a;
}
__device__ __forceinline__ void cp_async16(uint32_t dst, const void* src) {
    asm volatile("cp.async.cg.shared.global [%0], [%1], 16;" :: "r"(dst), "l"(src));
}
#define CP_COMMIT() asm volatile("cp.async.commit_group;" ::: "memory")
#define CP_WAIT(n)  asm volatile("cp.async.wait_group %0;" :: "n"(n) : "memory")

// ===========================================================================
// Mask dtype detection + bias precompute (log2 domain)
// ===========================================================================
__global__ void detect_mask_kernel(const unsigned char* __restrict__ mask)
{
    __shared__ unsigned int orr[4][256];
    const int tid = threadIdx.x;
    unsigned int o0 = 0, o1 = 0, o2 = 0, o3 = 0;
    for (int i = tid * 4; i < Bb * Ts; i += 256 * 4) {
        o0 |= mask[i + 0]; o1 |= mask[i + 1]; o2 |= mask[i + 2]; o3 |= mask[i + 3];
    }
    orr[0][tid] = o0; orr[1][tid] = o1; orr[2][tid] = o2; orr[3][tid] = o3;
    __syncthreads();
    for (int s = 128; s; s >>= 1) {
        if (tid < s) {
            orr[0][tid] |= orr[0][tid + s];
            orr[1][tid] |= orr[1][tid + s];
            orr[2][tid] |= orr[2][tid + s];
            orr[3][tid] |= orr[3][tid + s];
        }
        __syncthreads();
    }
    if (tid == 0) {
        unsigned int l0 = orr[0][0], l1 = orr[1][0], l2 = orr[2][0], l3 = orr[3][0];
        int mode;
        if ((l1 | l2 | l3) == 0u) mode = 1;
        else if ((l0 | l1) == 0u && (l2 | l3) != 0u) mode = 2;
        else mode = 0;
        g_maskMode = mode;
    }
}

__global__ void bias_kernel(const float* __restrict__ eng, const void* __restrict__ mask)
{
    const int kk = blockIdx.x * 256 + threadIdx.x;
    if (kk >= Bb * Ts) return;
    const int mode = g_maskMode;
    bool m;
    if (mode == 1)      m = ((const int*)mask)[kk] != 0;
    else if (mode == 2) m = ((const float*)mask)[kk] != 0.f;
    else                m = ((const unsigned char*)mask)[kk] != 0;
    g_bias[kk] = m ? -1e9f : log2f(fmaxf(eng[kk], 1e-6f));
}

// ===========================================================================
// Fused fp16 fragment packing: one launch covers x(A), qkv_w(B), out_w(B).
// ===========================================================================
__device__ __forceinline__ void pack_a_body(const float* __restrict__ src,
                                            uint4* __restrict__ dst, int M, int K,
                                            int blk, int nblk)
{
    const int K16 = K >> 4;
    const int total = (M >> 4) * K16 * 32;
    for (int q = blk * 256 + threadIdx.x; q < total; q += nblk * 256) {
        const int lane = q & 31;
        const int rs = q >> 5;
        const int S = rs % K16;
        const int R = rs / K16;
        const int g = lane >> 2, t = lane & 3;
        const float* p = src + (size_t)(R * 16 + g) * K + S * 16 + 2 * t;
        const float* p2 = p + (size_t)8 * K;
        const float2 a0 = *(const float2*)(p);
        const float2 a1 = *(const float2*)(p2);
        const float2 a2 = *(const float2*)(p + 8);
        const float2 a3 = *(const float2*)(p2 + 8);
        uint4 w;
        w.x = packf16(a0.x, a0.y);
        w.y = packf16(a1.x, a1.y);
        w.z = packf16(a2.x, a2.y);
        w.w = packf16(a3.x, a3.y);
        dst[q] = w;
    }
}

__device__ __forceinline__ void pack_b_body(const float* __restrict__ src,
                                            uint4* __restrict__ dst, int N, int K,
                                            int blk, int nblk)
{
    const int K32 = K >> 5;
    const int total = (N >> 3) * K32 * 32;
    for (int q = blk * 256 + threadIdx.x; q < total; q += nblk * 256) {
        const int lane = q & 31;
        const int cs = q >> 5;
        const int S = cs % K32;
        const int C = cs / K32;
        const int g = lane >> 2, t = lane & 3;
        const float* p = src + (size_t)(C * 8 + g) * K + S * 32 + 2 * t;
        const float2 b0 = *(const float2*)(p);
        const float2 b1 = *(const float2*)(p + 8);
        const float2 b2 = *(const float2*)(p + 16);
        const float2 b3 = *(const float2*)(p + 24);
        uint4 w;
        w.x = packf16(b0.x, b0.y);
        w.y = packf16(b1.x, b1.y);
        w.z = packf16(b2.x, b2.y);
        w.w = packf16(b3.x, b3.y);
        dst[q] = w;
    }
}

__global__ void __launch_bounds__(256)
pack_all_kernel(const float* __restrict__ x, const float* __restrict__ qkv_w,
                const float* __restrict__ out_w,
                uint4* __restrict__ xp, uint4* __restrict__ wq, uint4* __restrict__ wo)
{
    const int bx = blockIdx.x;
    if (bx < 2048)       pack_a_body(x,     xp, M_ROWS, Dd, bx,        2048);
    else if (bx < 3584)  pack_b_body(qkv_w, wq, QKV_N,  Dd, bx - 2048, 1536);
    else                 pack_b_body(out_w, wo, Dd,     Dd, bx - 3584, 512);
}

// ===========================================================================
// GEMM: 128x128 CTA tile, 4 warps x 64x64 warp tiles, BK=32, 4-stage cp.async.
// ===========================================================================
#define GP_SMEM_BYTES 65536

__global__ void __launch_bounds__(128, 2)
f16_gemm_packed(const uint4* __restrict__ Ap, const uint4* __restrict__ Bp,
                const float* __restrict__ bias, float* __restrict__ C,
                int K, int ldc)
{
    extern __shared__ uint4 ps[];
    uint4* sA = ps;
    uint4* sB = ps + 2048;
    const uint32_t sAaddr = smem_u32(sA);
    const uint32_t sBaddr = smem_u32(sB);

    const int tid  = threadIdx.x;
    const int wid  = tid >> 5;
    const int lane = tid & 31;
    const int g = lane >> 2, t = lane & 3;
    const int wm = wid & 1;
    const int wn = wid >> 1;
    const int bm = blockIdx.y * 128;
    const int bn = blockIdx.x * 128;
    const int K16 = K >> 4;
    const int K32 = K >> 5;
    const int Rb = bm >> 4;
    const int Cb = bn >> 3;

    float acc[4][8][4];
#pragma unroll
    for (int mi = 0; mi < 4; ++mi)
#pragma unroll
        for (int ni = 0; ni < 8; ++ni)
#pragma unroll
            for (int r = 0; r < 4; ++r) acc[mi][ni][r] = 0.f;

    auto issue = [&](int buf, int kt) {
#pragma unroll
        for (int i = 0; i < 4; ++i) {
            const int l    = tid + 128 * i;
            const int tile = l >> 5;
            const int ln   = l & 31;
            cp_async16(sAaddr + buf * 8192 + l * 16,
                       Ap + ((size_t)(Rb + (tile >> 1)) * K16 + 2 * kt + (tile & 1)) * 32 + ln);
            cp_async16(sBaddr + buf * 8192 + l * 16,
                       Bp + ((size_t)(Cb + tile) * K32 + kt) * 32 + ln);
        }
    };

    const int nChunks = K >> 5;
#pragma unroll
    for (int p = 0; p < 3; ++p) {
        if (p < nChunks) { issue(p, p); CP_COMMIT(); }
    }

    for (int kt = 0; kt < nChunks; ++kt) {
        if (kt + 3 < nChunks) {
            issue((kt + 3) & 3, kt + 3);
            CP_COMMIT();
            CP_WAIT(3);
        } else if (kt + 2 < nChunks) { CP_WAIT(2); }
        else if (kt + 1 < nChunks)   { CP_WAIT(1); }
        else                         { CP_WAIT(0); }
        __syncthreads();

        const uint4* bufA = sA + (kt & 3) * 512;
        const uint4* bufB = sB + (kt & 3) * 512;
        uint4 fa[4][2];
#pragma unroll
        for (int mi = 0; mi < 4; ++mi)
#pragma unroll
            for (int kc = 0; kc < 2; ++kc)
                fa[mi][kc] = bufA[(((wm * 4 + mi) << 1) | kc) * 32 + lane];
#pragma unroll
        for (int ni = 0; ni < 8; ++ni) {
            const uint4 f = bufB[(wn * 8 + ni) * 32 + lane];
#pragma unroll
            for (int mi = 0; mi < 4; ++mi) {
                mma_f16q(acc[mi][ni], fa[mi][0], f.x, f.y);
                mma_f16q(acc[mi][ni], fa[mi][1], f.z, f.w);
            }
        }
        __syncthreads();
    }

#pragma unroll
    for (int mi = 0; mi < 4; ++mi) {
        const int row = bm + wm * 64 + mi * 16 + g;
#pragma unroll
        for (int ni = 0; ni < 8; ++ni) {
            const int col = bn + wn * 64 + ni * 8 + 2 * t;
            const float b0 = bias[col];
            const float b1 = bias[col + 1];
            float2 lo, hi;
            lo.x = acc[mi][ni][0] + b0; lo.y = acc[mi][ni][1] + b1;
            hi.x = acc[mi][ni][2] + b0; hi.y = acc[mi][ni][3] + b1;
            *(float2*)(C + (size_t)row * ldc + col) = lo;
            *(float2*)(C + (size_t)(row + 8) * ldc + col) = hi;
        }
    }
}

// ===========================================================================
// Fused QKV GEMM (round 15, unchanged): 4 warps x 64x64, fused epilogues.
// ===========================================================================
__global__ void __launch_bounds__(128, 2)
qkv_gemm_fused(const uint4* __restrict__ Ap, const uint4* __restrict__ Bp,
               const float* __restrict__ bias,
               uint4* __restrict__ Qp, uint4* __restrict__ Kq, uint4* __restrict__ Vq)
{
    extern __shared__ uint4 ps[];
    uint4* sA = ps;
    uint4* sB = ps + 2048;
    const uint32_t sAaddr = smem_u32(sA);
    const uint32_t sBaddr = smem_u32(sB);

    const int tid  = threadIdx.x;
    const int wid  = tid >> 5;
    const int lane = tid & 31;
    const int g = lane >> 2, t = lane & 3;
    const int wm = wid & 1;
    const int wn = wid >> 1;
    const int bm = blockIdx.y * 128;
    const int bn = blockIdx.x * 128;
    const int K16 = Dd >> 4;
    const int K32 = Dd >> 5;
    const int Rb = bm >> 4;
    const int Cb = bn >> 3;

    float acc[4][8][4];
#pragma unroll
    for (int mi = 0; mi < 4; ++mi)
#pragma unroll
        for (int ni = 0; ni < 8; ++ni)
#pragma unroll
            for (int r = 0; r < 4; ++r) acc[mi][ni][r] = 0.f;

    auto issue = [&](int buf, int kt) {
#pragma unroll
        for (int i = 0; i < 4; ++i) {
            const int l    = tid + 128 * i;
            const int tile = l >> 5;
            const int ln   = l & 31;
            cp_async16(sAaddr + buf * 8192 + l * 16,
                       Ap + ((size_t)(Rb + (tile >> 1)) * K16 + 2 * kt + (tile & 1)) * 32 + ln);
            cp_async16(sBaddr + buf * 8192 + l * 16,
                       Bp + ((size_t)(Cb + tile) * K32 + kt) * 32 + ln);
        }
    };

    const int nChunks = Dd >> 5;
#pragma unroll
    for (int p = 0; p < 3; ++p) { issue(p, p); CP_COMMIT(); }

    for (int kt = 0; kt < nChunks; ++kt) {
        if (kt + 3 < nChunks) {
            issue((kt + 3) & 3, kt + 3);
            CP_COMMIT();
            CP_WAIT(3);
        } else if (kt + 2 < nChunks) { CP_WAIT(2); }
        else if (kt + 1 < nChunks)   { CP_WAIT(1); }
        else                         { CP_WAIT(0); }
        __syncthreads();

        const uint4* bufA = sA + (kt & 3) * 512;
        const uint4* bufB = sB + (kt & 3) * 512;
        uint4 fa[4][2];
#pragma unroll
        for (int mi = 0; mi < 4; ++mi)
#pragma unroll
            for (int kc = 0; kc < 2; ++kc)
                fa[mi][kc] = bufA[(((wm * 4 + mi) << 1) | kc) * 32 + lane];
#pragma unroll
        for (int ni = 0; ni < 8; ++ni) {
            const uint4 f = bufB[(wn * 8 + ni) * 32 + lane];
#pragma unroll
            for (int mi = 0; mi < 4; ++mi) {
                mma_f16q(acc[mi][ni], fa[mi][0], f.x, f.y);
                mma_f16q(acc[mi][ni], fa[mi][1], f.z, f.w);
            }
        }
        __syncthreads();
    }

    const int region = blockIdx.x >> 3;

    if (region == 0) {
#pragma unroll
        for (int mi = 0; mi < 4; ++mi) {
            const int R = Rb + wm * 4 + mi;
#pragma unroll
            for (int s = 0; s < 4; ++s) {
                const int colb = bn + wn * 64 + s * 16;
                const float b0 = bias[colb + 2 * t];
                const float b1 = bias[colb + 2 * t + 1];
                const float b2 = bias[colb + 8 + 2 * t];
                const float b3 = bias[colb + 8 + 2 * t + 1];
                uint4 w;
                w.x = packf16(acc[mi][2 * s][0] + b0,     acc[mi][2 * s][1] + b1);
                w.y = packf16(acc[mi][2 * s][2] + b0,     acc[mi][2 * s][3] + b1);
                w.z = packf16(acc[mi][2 * s + 1][0] + b2, acc[mi][2 * s + 1][1] + b3);
                w.w = packf16(acc[mi][2 * s + 1][2] + b2, acc[mi][2 * s + 1][3] + b3);
                const int Scol = blockIdx.x * 8 + wn * 4 + s;
                Qp[((size_t)R * 64 + Scol) * 32 + lane] = w;
            }
        }
    } else if (region == 1) {
        const int h = (blockIdx.x - 8) * 2 + wn;
#pragma unroll
        for (int mi = 0; mi < 4; ++mi) {
            const int rowbase = bm + wm * 64 + mi * 16;
            const int bb  = rowbase >> 11;
            const int tok = rowbase & 2047;
            const int kt  = tok >> 6;
            const int nt0 = (tok >> 3) & 7;
            const size_t base = ((size_t)(bb * Hh + h) * 32 + kt) * 512;
#pragma unroll
            for (int ksp = 0; ksp < 2; ++ksp) {
                const int colb = bn + wn * 64 + 32 * ksp;
                float bb0[4], bb1[4];
#pragma unroll
                for (int j = 0; j < 4; ++j) {
                    bb0[j] = bias[colb + 8 * j + 2 * t];
                    bb1[j] = bias[colb + 8 * j + 2 * t + 1];
                }
                uint4 w0, w1;
                w0.x = packf16(acc[mi][4 * ksp + 0][0] + bb0[0], acc[mi][4 * ksp + 0][1] + bb1[0]);
                w0.y = packf16(acc[mi][4 * ksp + 1][0] + bb0[1], acc[mi][4 * ksp + 1][1] + bb1[1]);
                w0.z = packf16(acc[mi][4 * ksp + 2][0] + bb0[2], acc[mi][4 * ksp + 2][1] + bb1[2]);
                w0.w = packf16(acc[mi][4 * ksp + 3][0] + bb0[3], acc[mi][4 * ksp + 3][1] + bb1[3]);
                w1.x = packf16(acc[mi][4 * ksp + 0][2] + bb0[0], acc[mi][4 * ksp + 0][3] + bb1[0]);
                w1.y = packf16(acc[mi][4 * ksp + 1][2] + bb0[1], acc[mi][4 * ksp + 1][3] + bb1[1]);
                w1.z = packf16(acc[mi][4 * ksp + 2][2] + bb0[2], acc[mi][4 * ksp + 2][3] + bb1[2]);
                w1.w = packf16(acc[mi][4 * ksp + 3][2] + bb0[3], acc[mi][4 * ksp + 3][3] + bb1[3]);
                Kq[base + ((size_t)(nt0 * 2 + ksp)) * 32 + lane] = w0;
                Kq[base + ((size_t)((nt0 + 1) * 2 + ksp)) * 32 + lane] = w1;
            }
        }
    } else {
        unsigned short* sT = (unsigned short*)ps;
#pragma unroll
        for (int mi = 0; mi < 4; ++mi) {
            const int r0 = wm * 64 + mi * 16 + g;
#pragma unroll
            for (int ni = 0; ni < 8; ++ni) {
                const int c = wn * 64 + ni * 8 + 2 * t;
                const float b0 = bias[bn + c];
                const float b1 = bias[bn + c + 1];
                *(uint32_t*)&sT[r0 * 136 + c]       = packf16(acc[mi][ni][0] + b0, acc[mi][ni][1] + b1);
                *(uint32_t*)&sT[(r0 + 8) * 136 + c] = packf16(acc[mi][ni][2] + b0, acc[mi][ni][3] + b1);
            }
        }
        __syncthreads();

        const int bb   = bm >> 11;
        const int tokb = bm & 2047;
#pragma unroll
        for (int i = 0; i < 16; ++i) {
            const int q6   = i * 4 + (tid >> 5);
            const int head = q6 >> 5;
            const int kt2  = (q6 >> 4) & 1;
            const int kp   = (q6 >> 2) & 3;
            const int nd2  = q6 & 3;
            const int r0 = kt2 * 64 + kp * 16 + 2 * t;
            const int c0 = head * 64 + nd2 * 16 + g;
            uint4 w;
            w.x = (uint32_t)sT[r0 * 136 + c0]           | ((uint32_t)sT[(r0 + 1) * 136 + c0] << 16);
            w.y = (uint32_t)sT[(r0 + 8) * 136 + c0]     | ((uint32_t)sT[(r0 + 9) * 136 + c0] << 16);
            w.z = (uint32_t)sT[r0 * 136 + c0 + 8]       | ((uint32_t)sT[(r0 + 1) * 136 + c0 + 8] << 16);
            w.w = (uint32_t)sT[(r0 + 8) * 136 + c0 + 8] | ((uint32_t)sT[(r0 + 9) * 136 + c0 + 8] << 16);
            const int hg  = (blockIdx.x - 16) * 2 + head;
            const int ktg = (tokb >> 6) + kt2;
            Vq[((size_t)(bb * Hh + hg) * 32 + ktg) * 512 + (kp * 4 + nd2) * 32 + lane] = w;
        }
    }
}

// ===========================================================================
// Flash attention: 32 queries/warp, 128 q / 128-thread CTA, 2-stage cp.async,
// ex2.f16x2 softmax. Row sums now via HADD2 trees (FMA pipe) instead of
// ones-B MMAs — frees 8 tensor MMAs per warp-tile.
// ===========================================================================
#define ATTN_SMEM_BYTES (2 * 8192 + 2 * 8192 + 2 * 256)
#define C1 0.18033688011112042f   // 0.125 * log2(e)

__global__ void __launch_bounds__(128, 2)
attn_kernel(const uint4* __restrict__ Qp, uint4* __restrict__ Opacked)
{
    extern __shared__ uint4 asm4[];
    uint4* sK = asm4;                      // [2][512]
    uint4* sV = asm4 + 1024;               // [2][512]
    float* sBias = (float*)(asm4 + 2048);  // [2][64]

    const uint32_t sKaddr = smem_u32(sK);
    const uint32_t sVaddr = smem_u32(sV);
    const uint32_t sBaddr = smem_u32(sBias);

    const int qt = blockIdx.x;
    const int h  = blockIdx.y;
    const int b  = blockIdx.z;
    const int tid  = threadIdx.x;
    const int warp = tid >> 5;
    const int lane = tid & 31;
    const int t = lane & 3;

    const size_t kvBase = ((size_t)(b * Hh + h)) * 32 * 512;
    const int R0 = (b * Ts + qt * 128 + warp * 32) >> 4;

    uint4 qf[2][4];
#pragma unroll
    for (int hf = 0; hf < 2; ++hf)
#pragma unroll
        for (int ks = 0; ks < 4; ++ks)
            qf[hf][ks] = Qp[((size_t)(R0 + hf) * 64 + h * 4 + ks) * 32 + lane];

    float o[2][8][4];
#pragma unroll
    for (int hf = 0; hf < 2; ++hf)
#pragma unroll
        for (int i = 0; i < 8; ++i)
#pragma unroll
            for (int j = 0; j < 4; ++j) o[hf][i][j] = 0.f;
    float lacc[2][2] = {{0.f, 0.f}, {0.f, 0.f}};   // [hf][row g / row g+8]

    auto issue = [&](int buf, int kt) {
        const uint4* srcK = g_Kq + kvBase + (size_t)kt * 512 + tid;
        const uint4* srcV = g_Vq + kvBase + (size_t)kt * 512 + tid;
        const uint32_t dK = sKaddr + buf * 8192 + tid * 16;
        const uint32_t dV = sVaddr + buf * 8192 + tid * 16;
#pragma unroll
        for (int i = 0; i < 4; ++i) {
            cp_async16(dK + i * 2048, srcK + i * 128);
            cp_async16(dV + i * 2048, srcV + i * 128);
        }
        if (tid < 16) cp_async16(sBaddr + buf * 256 + tid * 16, g_bias + b * Ts + kt * 64 + tid * 4);
    };

    issue(0, 0);
    CP_COMMIT();

    for (int kt = 0; kt < Ts / 64; ++kt) {
        const int buf = kt & 1;
        if (kt + 1 < Ts / 64) {
            issue(buf ^ 1, kt + 1);
            CP_COMMIT();
            CP_WAIT(1);
        } else {
            CP_WAIT(0);
        }
        __syncthreads();

        const uint4* bK = sK + buf * 512;
        const uint4* bV = sV + buf * 512;
        const float* bB = sBias + buf * 64;

        // ---- S = Q K^T (fp16) ----
        float sacc[2][8][4];
#pragma unroll
        for (int hf = 0; hf < 2; ++hf)
#pragma unroll
            for (int nt = 0; nt < 8; ++nt)
#pragma unroll
                for (int j = 0; j < 4; ++j) sacc[hf][nt][j] = 0.f;
#pragma unroll
        for (int ksp = 0; ksp < 2; ++ksp) {
#pragma unroll
            for (int nt = 0; nt < 8; ++nt) {
                const uint4 f = bK[(nt * 2 + ksp) * 32 + lane];
                mma_f16q(sacc[0][nt], qf[0][2 * ksp], f.x, f.y);
                mma_f16q(sacc[0][nt], qf[0][2 * ksp + 1], f.z, f.w);
                mma_f16q(sacc[1][nt], qf[1][2 * ksp], f.x, f.y);
                mma_f16q(sacc[1][nt], qf[1][2 * ksp + 1], f.z, f.w);
            }
        }

        // ---- softmax weights + HADD2 row-sum trees (off the tensor pipe) ----
        uint32_t ph[2][8][2];
#pragma unroll
        for (int nt = 0; nt < 8; ++nt) {
            const float2 bb2 = *(const float2*)(bB + 8 * nt + 2 * t);
#pragma unroll
            for (int hf = 0; hf < 2; ++hf) {
                const float a0 = fmaf(sacc[hf][nt][0], C1, bb2.x);
                const float a1 = fmaf(sacc[hf][nt][1], C1, bb2.y);
                const float a2 = fmaf(sacc[hf][nt][2], C1, bb2.x);
                const float a3 = fmaf(sacc[hf][nt][3], C1, bb2.y);
                ph[hf][nt][0] = ex2_f16x2(packf16(a0, a1));
                ph[hf][nt][1] = ex2_f16x2(packf16(a2, a3));
            }
        }
#pragma unroll
        for (int hf = 0; hf < 2; ++hf) {
            __half2 s0 = *(const __half2*)&ph[hf][0][0];
            __half2 s1 = *(const __half2*)&ph[hf][0][1];
#pragma unroll
            for (int nt = 1; nt < 8; ++nt) {
                s0 = __hadd2(s0, *(const __half2*)&ph[hf][nt][0]);
                s1 = __hadd2(s1, *(const __half2*)&ph[hf][nt][1]);
            }
            lacc[hf][0] += __low2float(s0) + __high2float(s0);
            lacc[hf][1] += __low2float(s1) + __high2float(s1);
        }

        // ---- O += P V (fp16) ----
#pragma unroll
        for (int kp = 0; kp < 4; ++kp) {
            const uint32_t a0[4] = { ph[0][2 * kp][0], ph[0][2 * kp][1],
                                     ph[0][2 * kp + 1][0], ph[0][2 * kp + 1][1] };
            const uint32_t a1[4] = { ph[1][2 * kp][0], ph[1][2 * kp][1],
                                     ph[1][2 * kp + 1][0], ph[1][2 * kp + 1][1] };
#pragma unroll
            for (int nd2 = 0; nd2 < 4; ++nd2) {
                const uint4 f = bV[(kp * 4 + nd2) * 32 + lane];
                mma_f16(o[0][2 * nd2], a0, f.x, f.y);
                mma_f16(o[0][2 * nd2 + 1], a0, f.z, f.w);
                mma_f16(o[1][2 * nd2], a1, f.x, f.y);
                mma_f16(o[1][2 * nd2 + 1], a1, f.z, f.w);
            }
        }
        __syncthreads();
    }

    // cross-t reduction of row sums (4 lanes per row group)
#pragma unroll
    for (int hf = 0; hf < 2; ++hf)
#pragma unroll
        for (int r = 0; r < 2; ++r) {
            lacc[hf][r] += __shfl_xor_sync(0xffffffffu, lacc[hf][r], 1);
            lacc[hf][r] += __shfl_xor_sync(0xffffffffu, lacc[hf][r], 2);
        }

#pragma unroll
    for (int hf = 0; hf < 2; ++hf) {
        const float inv0 = 1.0f / lacc[hf][0];
        const float inv1 = 1.0f / lacc[hf][1];
#pragma unroll
        for (int sd = 0; sd < 4; ++sd) {
            uint4 w;
            w.x = packf16(o[hf][2 * sd][0] * inv0,     o[hf][2 * sd][1] * inv0);
            w.y = packf16(o[hf][2 * sd][2] * inv1,     o[hf][2 * sd][3] * inv1);
            w.z = packf16(o[hf][2 * sd + 1][0] * inv0, o[hf][2 * sd + 1][1] * inv0);
            w.w = packf16(o[hf][2 * sd + 1][2] * inv1, o[hf][2 * sd + 1][3] * inv1);
            Opacked[((size_t)(R0 + hf) * 64 + h * 4 + sd) * 32 + lane] = w;
        }
    }
}

// ===========================================================================
extern "C" void kernel_launch(void* const* d_in, const int* in_sizes, int n_in,
                              void* d_out, int out_size)
{
    const float* x     = (const float*)d_in[0];
    const float* eng   = (const float*)d_in[1];
    const void*  mask  = (const void*)d_in[2];
    const float* qkv_w = (const float*)d_in[3];
    const float* qkv_b = (const float*)d_in[4];
    const float* out_w = (const float*)d_in[5];
    const float* out_b = (const float*)d_in[6];
    float* out = (float*)d_out;

    uint4 *qp = nullptr, *kq = nullptr, *vq = nullptr;
    uint4 *xp = nullptr, *op = nullptr, *wq = nullptr, *wo = nullptr;
    cudaGetSymbolAddress((void**)&qp, g_qp);
    cudaGetSymbolAddress((void**)&kq, g_Kq);
    cudaGetSymbolAddress((void**)&vq, g_Vq);
    cudaGetSymbolAddress((void**)&xp, g_xp);
    cudaGetSymbolAddress((void**)&op, g_op);
    cudaGetSymbolAddress((void**)&wq, g_wq);
    cudaGetSymbolAddress((void**)&wo, g_wo);

    cudaFuncSetAttribute(f16_gemm_packed,
                         cudaFuncAttributeMaxDynamicSharedMemorySize, GP_SMEM_BYTES);
    cudaFuncSetAttribute(qkv_gemm_fused,
                         cudaFuncAttributeMaxDynamicSharedMemorySize, GP_SMEM_BYTES);
    cudaFuncSetAttribute(attn_kernel,
                         cudaFuncAttributeMaxDynamicSharedMemorySize, ATTN_SMEM_BYTES);

    // 0) mask dtype detection + per-key bias precompute (log2 domain)
    detect_mask_kernel<<<1, 256>>>((const unsigned char*)mask);
    bias_kernel<<<(Bb * Ts + 255) / 256, 256>>>(eng, mask);

    // 0b) single fused pack launch: x (A-pack) + both weights (B-packs)
    pack_all_kernel<<<4096, 256>>>(x, qkv_w, out_w, xp, wq, wo);

    // 1) fused QKV projection -> Q A-pack, K B-pack, V frag tiles
    dim3 g1(QKV_N / 128, M_ROWS / 128);
    qkv_gemm_fused<<<g1, 128, GP_SMEM_BYTES>>>(xp, wq, qkv_b, qp, kq, vq);

    // 2) attention: 128 queries / CTA, 32 per warp, HADD2 row sums
    dim3 g2(Ts / 128, Hh, Bb);
    attn_kernel<<<g2, 128, ATTN_SMEM_BYTES>>>(qp, op);

    // 3) output projection (4 warps x 64x64, 4-stage pipeline)
    dim3 g3(Dd / 128, M_ROWS / 128);
    f16_gemm_packed<<<g3, 128, GP_SMEM_BYTES>>>(op, wo, out_b, out, Dd, Dd);
}

// round 17
// speedup vs baseline: 1.1458x; 1.0016x over previous
#include <cuda_runtime.h>
#include <cuda_bf16.h>
#include <cuda_fp16.h>
#include <math.h>
#include <stdint.h>

// Problem constants
#define Bb 4
#define Ts 2048
#define Dd 1024
#define Hh 16
#define HD 64
#define M_ROWS 8192
#define QKV_N 3072

// Scratch (device globals: allocation-free)
__device__ float g_bias[Bb * Ts];
__device__ int   g_maskMode;
__device__ uint4 g_qp[(size_t)(M_ROWS / 16) * 64 * 32];
__device__ uint4 g_Kq[(size_t)Bb * Hh * 32 * 512];
__device__ uint4 g_Vq[(size_t)Bb * Hh * 32 * 512];
__device__ uint4 g_xp[(size_t)(M_ROWS / 16) * 64 * 32];
__device__ uint4 g_op[(size_t)(M_ROWS / 16) * 64 * 32];
__device__ uint4 g_wq[(size_t)(QKV_N / 8) * 32 * 32];
__device__ uint4 g_wo[(size_t)(Dd / 8) * 32 * 32];

// ===========================================================================
// helpers
// ===========================================================================
__device__ __forceinline__ uint32_t packf16(float lo, float hi) {
    uint32_t r;
    asm("cvt.rn.f16x2.f32 %0, %1, %2;" : "=r"(r) : "f"(hi), "f"(lo));
    return r;
}
__device__ __forceinline__ uint32_t ex2_f16x2(uint32_t x) {
    uint32_t r;
    asm("ex2.approx.f16x2 %0, %1;" : "=r"(r) : "r"(x));
    return r;
}

__device__ __forceinline__ void mma_f16(float* c, const uint32_t* a, uint32_t b0, uint32_t b1) {
    asm volatile(
        "mma.sync.aligned.m16n8k16.row.col.f32.f16.f16.f32 "
        "{%0,%1,%2,%3}, {%4,%5,%6,%7}, {%8,%9}, {%0,%1,%2,%3};\n"
        : "+f"(c[0]), "+f"(c[1]), "+f"(c[2]), "+f"(c[3])
        : "r"(a[0]), "r"(a[1]), "r"(a[2]), "r"(a[3]), "r"(b0), "r"(b1));
}
__device__ __forceinline__ void mma_f16q(float* c, const uint4& a, uint32_t b0, uint32_t b1) {
    asm volatile(
        "mma.sync.aligned.m16n8k16.row.col.f32.f16.f16.f32 "
        "{%0,%1,%2,%3}, {%4,%5,%6,%7}, {%8,%9}, {%0,%1,%2,%3};\n"
        : "+f"(c[0]), "+f"(c[1]), "+f"(c[2]), "+f"(c[3])
        : "r"(a.x), "r"(a.y), "r"(a.z), "r"(a.w), "r"(b0), "r"(b1));
}

__device__ __forceinline__ uint32_t smem_u32(const void* p) {
    uint32_t a;
    asm("{ .reg .u64 t; cvta.to.shared.u64 t, %1; cvt.u32.u64 %0, t; }" : "=r"(a) : "l"(p));
    return a;
}
__device__ __forceinline__ void cp_async16(uint32_t dst, const void* src) {
    asm volatile("cp.async.cg.shared.global [%0], [%1], 16;" :: "r"(dst), "l"(src));
}
#define CP_COMMIT() asm volatile("cp.async.commit_group;" ::: "memory")
#define CP_WAIT(n)  asm volatile("cp.async.wait_group %0;" :: "n"(n) : "memory")

// ===========================================================================
// Mask dtype detection + bias precompute (log2 domain)
// ===========================================================================
__global__ void detect_mask_kernel(const unsigned char* __restrict__ mask)
{
    __shared__ unsigned int orr[4][256];
    const int tid = threadIdx.x;
    unsigned int o0 = 0, o1 = 0, o2 = 0, o3 = 0;
    for (int i = tid * 4; i < Bb * Ts; i += 256 * 4) {
        o0 |= mask[i + 0]; o1 |= mask[i + 1]; o2 |= mask[i + 2]; o3 |= mask[i + 3];
    }
    orr[0][tid] = o0; orr[1][tid] = o1; orr[2][tid] = o2; orr[3][tid] = o3;
    __syncthreads();
    for (int s = 128; s; s >>= 1) {
        if (tid < s) {
            orr[0][tid] |= orr[0][tid + s];
            orr[1][tid] |= orr[1][tid + s];
            orr[2][tid] |= orr[2][tid + s];
            orr[3][tid] |= orr[3][tid + s];
        }
        __syncthreads();
    }
    if (tid == 0) {
        unsigned int l0 = orr[0][0], l1 = orr[1][0], l2 = orr[2][0], l3 = orr[3][0];
        int mode;
        if ((l1 | l2 | l3) == 0u) mode = 1;
        else if ((l0 | l1) == 0u && (l2 | l3) != 0u) mode = 2;
        else mode = 0;
        g_maskMode = mode;
    }
}

__global__ void bias_kernel(const float* __restrict__ eng, const void* __restrict__ mask)
{
    const int kk = blockIdx.x * 256 + threadIdx.x;
    if (kk >= Bb * Ts) return;
    const int mode = g_maskMode;
    bool m;
    if (mode == 1)      m = ((const int*)mask)[kk] != 0;
    else if (mode == 2) m = ((const float*)mask)[kk] != 0.f;
    else                m = ((const unsigned char*)mask)[kk] != 0;
    g_bias[kk] = m ? -1e9f : log2f(fmaxf(eng[kk], 1e-6f));
}

// ===========================================================================
// Fused fp16 fragment packing
// ===========================================================================
__device__ __forceinline__ void pack_a_body(const float* __restrict__ src,
                                            uint4* __restrict__ dst, int M, int K,
                                            int blk, int nblk)
{
    const int K16 = K >> 4;
    const int total = (M >> 4) * K16 * 32;
    for (int q = blk * 256 + threadIdx.x; q < total; q += nblk * 256) {
        const int lane = q & 31;
        const int rs = q >> 5;
        const int S = rs % K16;
        const int R = rs / K16;
        const int g = lane >> 2, t = lane & 3;
        const float* p = src + (size_t)(R * 16 + g) * K + S * 16 + 2 * t;
        const float* p2 = p + (size_t)8 * K;
        const float2 a0 = *(const float2*)(p);
        const float2 a1 = *(const float2*)(p2);
        const float2 a2 = *(const float2*)(p + 8);
        const float2 a3 = *(const float2*)(p2 + 8);
        uint4 w;
        w.x = packf16(a0.x, a0.y);
        w.y = packf16(a1.x, a1.y);
        w.z = packf16(a2.x, a2.y);
        w.w = packf16(a3.x, a3.y);
        dst[q] = w;
    }
}

__device__ __forceinline__ void pack_b_body(const float* __restrict__ src,
                                            uint4* __restrict__ dst, int N, int K,
                                            int blk, int nblk)
{
    const int K32 = K >> 5;
    const int total = (N >> 3) * K32 * 32;
    for (int q = blk * 256 + threadIdx.x; q < total; q += nblk * 256) {
        const int lane = q & 31;
        const int cs = q >> 5;
        const int S = cs % K32;
        const int C = cs / K32;
        const int g = lane >> 2, t = lane & 3;
        const float* p = src + (size_t)(C * 8 + g) * K + S * 32 + 2 * t;
        const float2 b0 = *(const float2*)(p);
        const float2 b1 = *(const float2*)(p + 8);
        const float2 b2 = *(const float2*)(p + 16);
        const float2 b3 = *(const float2*)(p + 24);
        uint4 w;
        w.x = packf16(b0.x, b0.y);
        w.y = packf16(b1.x, b1.y);
        w.z = packf16(b2.x, b2.y);
        w.w = packf16(b3.x, b3.y);
        dst[q] = w;
    }
}

__global__ void __launch_bounds__(256)
pack_all_kernel(const float* __restrict__ x, const float* __restrict__ qkv_w,
                const float* __restrict__ out_w,
                uint4* __restrict__ xp, uint4* __restrict__ wq, uint4* __restrict__ wo)
{
    const int bx = blockIdx.x;
    if (bx < 2048)       pack_a_body(x,     xp, M_ROWS, Dd, bx,        2048);
    else if (bx < 3584)  pack_b_body(qkv_w, wq, QKV_N,  Dd, bx - 2048, 1536);
    else                 pack_b_body(out_w, wo, Dd,     Dd, bx - 3584, 512);
}

// ===========================================================================
// GEMM: 128x128 CTA tile, 4 warps x 64x64, BK=32, 4-stage cp.async.
// MMA order: kc-split sweeps -> dependent accumulations 4 apart.
// ===========================================================================
#define GP_SMEM_BYTES 65536

__global__ void __launch_bounds__(128, 2)
f16_gemm_packed(const uint4* __restrict__ Ap, const uint4* __restrict__ Bp,
                const float* __restrict__ bias, float* __restrict__ C,
                int K, int ldc)
{
    extern __shared__ uint4 ps[];
    uint4* sA = ps;
    uint4* sB = ps + 2048;
    const uint32_t sAaddr = smem_u32(sA);
    const uint32_t sBaddr = smem_u32(sB);

    const int tid  = threadIdx.x;
    const int wid  = tid >> 5;
    const int lane = tid & 31;
    const int g = lane >> 2, t = lane & 3;
    const int wm = wid & 1;
    const int wn = wid >> 1;
    const int bm = blockIdx.y * 128;
    const int bn = blockIdx.x * 128;
    const int K16 = K >> 4;
    const int K32 = K >> 5;
    const int Rb = bm >> 4;
    const int Cb = bn >> 3;

    float acc[4][8][4];
#pragma unroll
    for (int mi = 0; mi < 4; ++mi)
#pragma unroll
        for (int ni = 0; ni < 8; ++ni)
#pragma unroll
            for (int r = 0; r < 4; ++r) acc[mi][ni][r] = 0.f;

    auto issue = [&](int buf, int kt) {
#pragma unroll
        for (int i = 0; i < 4; ++i) {
            const int l    = tid + 128 * i;
            const int tile = l >> 5;
            const int ln   = l & 31;
            cp_async16(sAaddr + buf * 8192 + l * 16,
                       Ap + ((size_t)(Rb + (tile >> 1)) * K16 + 2 * kt + (tile & 1)) * 32 + ln);
            cp_async16(sBaddr + buf * 8192 + l * 16,
                       Bp + ((size_t)(Cb + tile) * K32 + kt) * 32 + ln);
        }
    };

    const int nChunks = K >> 5;
#pragma unroll
    for (int p = 0; p < 3; ++p) {
        if (p < nChunks) { issue(p, p); CP_COMMIT(); }
    }

    for (int kt = 0; kt < nChunks; ++kt) {
        if (kt + 3 < nChunks) {
            issue((kt + 3) & 3, kt + 3);
            CP_COMMIT();
            CP_WAIT(3);
        } else if (kt + 2 < nChunks) { CP_WAIT(2); }
        else if (kt + 1 < nChunks)   { CP_WAIT(1); }
        else                         { CP_WAIT(0); }
        __syncthreads();

        const uint4* bufA = sA + (kt & 3) * 512;
        const uint4* bufB = sB + (kt & 3) * 512;
        uint4 fa[4][2];
#pragma unroll
        for (int mi = 0; mi < 4; ++mi)
#pragma unroll
            for (int kc = 0; kc < 2; ++kc)
                fa[mi][kc] = bufA[(((wm * 4 + mi) << 1) | kc) * 32 + lane];
#pragma unroll
        for (int ni = 0; ni < 8; ++ni) {
            const uint4 f = bufB[(wn * 8 + ni) * 32 + lane];
#pragma unroll
            for (int mi = 0; mi < 4; ++mi)
                mma_f16q(acc[mi][ni], fa[mi][0], f.x, f.y);
#pragma unroll
            for (int mi = 0; mi < 4; ++mi)
                mma_f16q(acc[mi][ni], fa[mi][1], f.z, f.w);
        }
        __syncthreads();
    }

#pragma unroll
    for (int mi = 0; mi < 4; ++mi) {
        const int row = bm + wm * 64 + mi * 16 + g;
#pragma unroll
        for (int ni = 0; ni < 8; ++ni) {
            const int col = bn + wn * 64 + ni * 8 + 2 * t;
            const float b0 = bias[col];
            const float b1 = bias[col + 1];
            float2 lo, hi;
            lo.x = acc[mi][ni][0] + b0; lo.y = acc[mi][ni][1] + b1;
            hi.x = acc[mi][ni][2] + b0; hi.y = acc[mi][ni][3] + b1;
            *(float2*)(C + (size_t)row * ldc + col) = lo;
            *(float2*)(C + (size_t)(row + 8) * ldc + col) = hi;
        }
    }
}

// ===========================================================================
// Fused QKV GEMM: 4 warps x 64x64, kc-split MMA order, fused epilogues.
// ===========================================================================
__global__ void __launch_bounds__(128, 2)
qkv_gemm_fused(const uint4* __restrict__ Ap, const uint4* __restrict__ Bp,
               const float* __restrict__ bias,
               uint4* __restrict__ Qp, uint4* __restrict__ Kq, uint4* __restrict__ Vq)
{
    extern __shared__ uint4 ps[];
    uint4* sA = ps;
    uint4* sB = ps + 2048;
    const uint32_t sAaddr = smem_u32(sA);
    const uint32_t sBaddr = smem_u32(sB);

    const int tid  = threadIdx.x;
    const int wid  = tid >> 5;
    const int lane = tid & 31;
    const int g = lane >> 2, t = lane & 3;
    const int wm = wid & 1;
    const int wn = wid >> 1;
    const int bm = blockIdx.y * 128;
    const int bn = blockIdx.x * 128;
    const int K16 = Dd >> 4;
    const int K32 = Dd >> 5;
    const int Rb = bm >> 4;
    const int Cb = bn >> 3;

    float acc[4][8][4];
#pragma unroll
    for (int mi = 0; mi < 4; ++mi)
#pragma unroll
        for (int ni = 0; ni < 8; ++ni)
#pragma unroll
            for (int r = 0; r < 4; ++r) acc[mi][ni][r] = 0.f;

    auto issue = [&](int buf, int kt) {
#pragma unroll
        for (int i = 0; i < 4; ++i) {
            const int l    = tid + 128 * i;
            const int tile = l >> 5;
            const int ln   = l & 31;
            cp_async16(sAaddr + buf * 8192 + l * 16,
                       Ap + ((size_t)(Rb + (tile >> 1)) * K16 + 2 * kt + (tile & 1)) * 32 + ln);
            cp_async16(sBaddr + buf * 8192 + l * 16,
                       Bp + ((size_t)(Cb + tile) * K32 + kt) * 32 + ln);
        }
    };

    const int nChunks = Dd >> 5;
#pragma unroll
    for (int p = 0; p < 3; ++p) { issue(p, p); CP_COMMIT(); }

    for (int kt = 0; kt < nChunks; ++kt) {
        if (kt + 3 < nChunks) {
            issue((kt + 3) & 3, kt + 3);
            CP_COMMIT();
            CP_WAIT(3);
        } else if (kt + 2 < nChunks) { CP_WAIT(2); }
        else if (kt + 1 < nChunks)   { CP_WAIT(1); }
        else                         { CP_WAIT(0); }
        __syncthreads();

        const uint4* bufA = sA + (kt & 3) * 512;
        const uint4* bufB = sB + (kt & 3) * 512;
        uint4 fa[4][2];
#pragma unroll
        for (int mi = 0; mi < 4; ++mi)
#pragma unroll
            for (int kc = 0; kc < 2; ++kc)
                fa[mi][kc] = bufA[(((wm * 4 + mi) << 1) | kc) * 32 + lane];
#pragma unroll
        for (int ni = 0; ni < 8; ++ni) {
            const uint4 f = bufB[(wn * 8 + ni) * 32 + lane];
#pragma unroll
            for (int mi = 0; mi < 4; ++mi)
                mma_f16q(acc[mi][ni], fa[mi][0], f.x, f.y);
#pragma unroll
            for (int mi = 0; mi < 4; ++mi)
                mma_f16q(acc[mi][ni], fa[mi][1], f.z, f.w);
        }
        __syncthreads();
    }

    const int region = blockIdx.x >> 3;

    if (region == 0) {
#pragma unroll
        for (int mi = 0; mi < 4; ++mi) {
            const int R = Rb + wm * 4 + mi;
#pragma unroll
            for (int s = 0; s < 4; ++s) {
                const int colb = bn + wn * 64 + s * 16;
                const float b0 = bias[colb + 2 * t];
                const float b1 = bias[colb + 2 * t + 1];
                const float b2 = bias[colb + 8 + 2 * t];
                const float b3 = bias[colb + 8 + 2 * t + 1];
                uint4 w;
                w.x = packf16(acc[mi][2 * s][0] + b0,     acc[mi][2 * s][1] + b1);
                w.y = packf16(acc[mi][2 * s][2] + b0,     acc[mi][2 * s][3] + b1);
                w.z = packf16(acc[mi][2 * s + 1][0] + b2, acc[mi][2 * s + 1][1] + b3);
                w.w = packf16(acc[mi][2 * s + 1][2] + b2, acc[mi][2 * s + 1][3] + b3);
                const int Scol = blockIdx.x * 8 + wn * 4 + s;
                Qp[((size_t)R * 64 + Scol) * 32 + lane] = w;
            }
        }
    } else if (region == 1) {
        const int h = (blockIdx.x - 8) * 2 + wn;
#pragma unroll
        for (int mi = 0; mi < 4; ++mi) {
            const int rowbase = bm + wm * 64 + mi * 16;
            const int bb  = rowbase >> 11;
            const int tok = rowbase & 2047;
            const int kt  = tok >> 6;
            const int nt0 = (tok >> 3) & 7;
            const size_t base = ((size_t)(bb * Hh + h) * 32 + kt) * 512;
#pragma unroll
            for (int ksp = 0; ksp < 2; ++ksp) {
                const int colb = bn + wn * 64 + 32 * ksp;
                float bb0[4], bb1[4];
#pragma unroll
                for (int j = 0; j < 4; ++j) {
                    bb0[j] = bias[colb + 8 * j + 2 * t];
                    bb1[j] = bias[colb + 8 * j + 2 * t + 1];
                }
                uint4 w0, w1;
                w0.x = packf16(acc[mi][4 * ksp + 0][0] + bb0[0], acc[mi][4 * ksp + 0][1] + bb1[0]);
                w0.y = packf16(acc[mi][4 * ksp + 1][0] + bb0[1], acc[mi][4 * ksp + 1][1] + bb1[1]);
                w0.z = packf16(acc[mi][4 * ksp + 2][0] + bb0[2], acc[mi][4 * ksp + 2][1] + bb1[2]);
                w0.w = packf16(acc[mi][4 * ksp + 3][0] + bb0[3], acc[mi][4 * ksp + 3][1] + bb1[3]);
                w1.x = packf16(acc[mi][4 * ksp + 0][2] + bb0[0], acc[mi][4 * ksp + 0][3] + bb1[0]);
                w1.y = packf16(acc[mi][4 * ksp + 1][2] + bb0[1], acc[mi][4 * ksp + 1][3] + bb1[1]);
                w1.z = packf16(acc[mi][4 * ksp + 2][2] + bb0[2], acc[mi][4 * ksp + 2][3] + bb1[2]);
                w1.w = packf16(acc[mi][4 * ksp + 3][2] + bb0[3], acc[mi][4 * ksp + 3][3] + bb1[3]);
                Kq[base + ((size_t)(nt0 * 2 + ksp)) * 32 + lane] = w0;
                Kq[base + ((size_t)((nt0 + 1) * 2 + ksp)) * 32 + lane] = w1;
            }
        }
    } else {
        unsigned short* sT = (unsigned short*)ps;
#pragma unroll
        for (int mi = 0; mi < 4; ++mi) {
            const int r0 = wm * 64 + mi * 16 + g;
#pragma unroll
            for (int ni = 0; ni < 8; ++ni) {
                const int c = wn * 64 + ni * 8 + 2 * t;
                const float b0 = bias[bn + c];
                const float b1 = bias[bn + c + 1];
                *(uint32_t*)&sT[r0 * 136 + c]       = packf16(acc[mi][ni][0] + b0, acc[mi][ni][1] + b1);
                *(uint32_t*)&sT[(r0 + 8) * 136 + c] = packf16(acc[mi][ni][2] + b0, acc[mi][ni][3] + b1);
            }
        }
        __syncthreads();

        const int bb   = bm >> 11;
        const int tokb = bm & 2047;
#pragma unroll
        for (int i = 0; i < 16; ++i) {
            const int q6   = i * 4 + (tid >> 5);
            const int head = q6 >> 5;
            const int kt2  = (q6 >> 4) & 1;
            const int kp   = (q6 >> 2) & 3;
            const int nd2  = q6 & 3;
            const int r0 = kt2 * 64 + kp * 16 + 2 * t;
            const int c0 = head * 64 + nd2 * 16 + g;
            uint4 w;
            w.x = (uint32_t)sT[r0 * 136 + c0]           | ((uint32_t)sT[(r0 + 1) * 136 + c0] << 16);
            w.y = (uint32_t)sT[(r0 + 8) * 136 + c0]     | ((uint32_t)sT[(r0 + 9) * 136 + c0] << 16);
            w.z = (uint32_t)sT[r0 * 136 + c0 + 8]       | ((uint32_t)sT[(r0 + 1) * 136 + c0 + 8] << 16);
            w.w = (uint32_t)sT[(r0 + 8) * 136 + c0 + 8] | ((uint32_t)sT[(r0 + 9) * 136 + c0 + 8] << 16);
            const int hg  = (blockIdx.x - 16) * 2 + head;
            const int ktg = (tokb >> 6) + kt2;
            Vq[((size_t)(bb * Hh + hg) * 32 + ktg) * 512 + (kp * 4 + nd2) * 32 + lane] = w;
        }
    }
}

// ===========================================================================
// Flash attention: 32 queries/warp, S-loop MMAs reordered for dependency
// distance, HADD2 row sums, ex2.f16x2 softmax.
// ===========================================================================
#define ATTN_SMEM_BYTES (2 * 8192 + 2 * 8192 + 2 * 256)
#define C1 0.18033688011112042f

__global__ void __launch_bounds__(128, 2)
attn_kernel(const uint4* __restrict__ Qp, uint4* __restrict__ Opacked)
{
    extern __shared__ uint4 asm4[];
    uint4* sK = asm4;
    uint4* sV = asm4 + 1024;
    float* sBias = (float*)(asm4 + 2048);

    const uint32_t sKaddr = smem_u32(sK);
    const uint32_t sVaddr = smem_u32(sV);
    const uint32_t sBaddr = smem_u32(sBias);

    const int qt = blockIdx.x;
    const int h  = blockIdx.y;
    const int b  = blockIdx.z;
    const int tid  = threadIdx.x;
    const int warp = tid >> 5;
    const int lane = tid & 31;
    const int t = lane & 3;

    const size_t kvBase = ((size_t)(b * Hh + h)) * 32 * 512;
    const int R0 = (b * Ts + qt * 128 + warp * 32) >> 4;

    uint4 qf[2][4];
#pragma unroll
    for (int hf = 0; hf < 2; ++hf)
#pragma unroll
        for (int ks = 0; ks < 4; ++ks)
            qf[hf][ks] = Qp[((size_t)(R0 + hf) * 64 + h * 4 + ks) * 32 + lane];

    float o[2][8][4];
#pragma unroll
    for (int hf = 0; hf < 2; ++hf)
#pragma unroll
        for (int i = 0; i < 8; ++i)
#pragma unroll
            for (int j = 0; j < 4; ++j) o[hf][i][j] = 0.f;
    float lacc[2][2] = {{0.f, 0.f}, {0.f, 0.f}};

    auto issue = [&](int buf, int kt) {
        const uint4* srcK = g_Kq + kvBase + (size_t)kt * 512 + tid;
        const uint4* srcV = g_Vq + kvBase + (size_t)kt * 512 + tid;
        const uint32_t dK = sKaddr + buf * 8192 + tid * 16;
        const uint32_t dV = sVaddr + buf * 8192 + tid * 16;
#pragma unroll
        for (int i = 0; i < 4; ++i) {
            cp_async16(dK + i * 2048, srcK + i * 128);
            cp_async16(dV + i * 2048, srcV + i * 128);
        }
        if (tid < 16) cp_async16(sBaddr + buf * 256 + tid * 16, g_bias + b * Ts + kt * 64 + tid * 4);
    };

    issue(0, 0);
    CP_COMMIT();

    for (int kt = 0; kt < Ts / 64; ++kt) {
        const int buf = kt & 1;
        if (kt + 1 < Ts / 64) {
            issue(buf ^ 1, kt + 1);
            CP_COMMIT();
            CP_WAIT(1);
        } else {
            CP_WAIT(0);
        }
        __syncthreads();

        const uint4* bK = sK + buf * 512;
        const uint4* bV = sV + buf * 512;
        const float* bB = sBias + buf * 64;

        // ---- S = Q K^T (fp16); kc-split order: same-acc MMAs 2 apart ----
        float sacc[2][8][4];
#pragma unroll
        for (int hf = 0; hf < 2; ++hf)
#pragma unroll
            for (int nt = 0; nt < 8; ++nt)
#pragma unroll
                for (int j = 0; j < 4; ++j) sacc[hf][nt][j] = 0.f;
#pragma unroll
        for (int ksp = 0; ksp < 2; ++ksp) {
#pragma unroll
            for (int nt = 0; nt < 8; ++nt) {
                const uint4 f = bK[(nt * 2 + ksp) * 32 + lane];
                mma_f16q(sacc[0][nt], qf[0][2 * ksp], f.x, f.y);
                mma_f16q(sacc[1][nt], qf[1][2 * ksp], f.x, f.y);
                mma_f16q(sacc[0][nt], qf[0][2 * ksp + 1], f.z, f.w);
                mma_f16q(sacc[1][nt], qf[1][2 * ksp + 1], f.z, f.w);
            }
        }

        // ---- softmax weights + HADD2 row-sum trees ----
        uint32_t ph[2][8][2];
#pragma unroll
        for (int nt = 0; nt < 8; ++nt) {
            const float2 bb2 = *(const float2*)(bB + 8 * nt + 2 * t);
#pragma unroll
            for (int hf = 0; hf < 2; ++hf) {
                const float a0 = fmaf(sacc[hf][nt][0], C1, bb2.x);
                const float a1 = fmaf(sacc[hf][nt][1], C1, bb2.y);
                const float a2 = fmaf(sacc[hf][nt][2], C1, bb2.x);
                const float a3 = fmaf(sacc[hf][nt][3], C1, bb2.y);
                ph[hf][nt][0] = ex2_f16x2(packf16(a0, a1));
                ph[hf][nt][1] = ex2_f16x2(packf16(a2, a3));
            }
        }
#pragma unroll
        for (int hf = 0; hf < 2; ++hf) {
            __half2 s0 = *(const __half2*)&ph[hf][0][0];
            __half2 s1 = *(const __half2*)&ph[hf][0][1];
#pragma unroll
            for (int nt = 1; nt < 8; ++nt) {
                s0 = __hadd2(s0, *(const __half2*)&ph[hf][nt][0]);
                s1 = __hadd2(s1, *(const __half2*)&ph[hf][nt][1]);
            }
            lacc[hf][0] += __low2float(s0) + __high2float(s0);
            lacc[hf][1] += __low2float(s1) + __high2float(s1);
        }

        // ---- O += P V (fp16) ----
#pragma unroll
        for (int kp = 0; kp < 4; ++kp) {
            const uint32_t a0[4] = { ph[0][2 * kp][0], ph[0][2 * kp][1],
                                     ph[0][2 * kp + 1][0], ph[0][2 * kp + 1][1] };
            const uint32_t a1[4] = { ph[1][2 * kp][0], ph[1][2 * kp][1],
                                     ph[1][2 * kp + 1][0], ph[1][2 * kp + 1][1] };
#pragma unroll
            for (int nd2 = 0; nd2 < 4; ++nd2) {
                const uint4 f = bV[(kp * 4 + nd2) * 32 + lane];
                mma_f16(o[0][2 * nd2], a0, f.x, f.y);
                mma_f16(o[0][2 * nd2 + 1], a0, f.z, f.w);
                mma_f16(o[1][2 * nd2], a1, f.x, f.y);
                mma_f16(o[1][2 * nd2 + 1], a1, f.z, f.w);
            }
        }
        __syncthreads();
    }

#pragma unroll
    for (int hf = 0; hf < 2; ++hf)
#pragma unroll
        for (int r = 0; r < 2; ++r) {
            lacc[hf][r] += __shfl_xor_sync(0xffffffffu, lacc[hf][r], 1);
            lacc[hf][r] += __shfl_xor_sync(0xffffffffu, lacc[hf][r], 2);
        }

#pragma unroll
    for (int hf = 0; hf < 2; ++hf) {
        const float inv0 = 1.0f / lacc[hf][0];
        const float inv1 = 1.0f / lacc[hf][1];
#pragma unroll
        for (int sd = 0; sd < 4; ++sd) {
            uint4 w;
            w.x = packf16(o[hf][2 * sd][0] * inv0,     o[hf][2 * sd][1] * inv0);
            w.y = packf16(o[hf][2 * sd][2] * inv1,     o[hf][2 * sd][3] * inv1);
            w.z = packf16(o[hf][2 * sd + 1][0] * inv0, o[hf][2 * sd + 1][1] * inv0);
            w.w = packf16(o[hf][2 * sd + 1][2] * inv1, o[hf][2 * sd + 1][3] * inv1);
            Opacked[((size_t)(R0 + hf) * 64 + h * 4 + sd) * 32 + lane] = w;
        }
    }
}

// ===========================================================================
extern "C" void kernel_launch(void* const* d_in, const int* in_sizes, int n_in,
                              void* d_out, int out_size)
{
    const float* x     = (const float*)d_in[0];
    const float* eng   = (const float*)d_in[1];
    const void*  mask  = (const void*)d_in[2];
    const float* qkv_w = (const float*)d_in[3];
    const float* qkv_b = (const float*)d_in[4];
    const float* out_w = (const float*)d_in[5];
    const float* out_b = (const float*)d_in[6];
    float* out = (float*)d_out;

    uint4 *qp = nullptr, *kq = nullptr, *vq = nullptr;
    uint4 *xp = nullptr, *op = nullptr, *wq = nullptr, *wo = nullptr;
    cudaGetSymbolAddress((void**)&qp, g_qp);
    cudaGetSymbolAddress((void**)&kq, g_Kq);
    cudaGetSymbolAddress((void**)&vq, g_Vq);
    cudaGetSymbolAddress((void**)&xp, g_xp);
    cudaGetSymbolAddress((void**)&op, g_op);
    cudaGetSymbolAddress((void**)&wq, g_wq);
    cudaGetSymbolAddress((void**)&wo, g_wo);

    cudaFuncSetAttribute(f16_gemm_packed,
                         cudaFuncAttributeMaxDynamicSharedMemorySize, GP_SMEM_BYTES);
    cudaFuncSetAttribute(qkv_gemm_fused,
                         cudaFuncAttributeMaxDynamicSharedMemorySize, GP_SMEM_BYTES);
    cudaFuncSetAttribute(attn_kernel,
                         cudaFuncAttributeMaxDynamicSharedMemorySize, ATTN_SMEM_BYTES);

    // 0) mask dtype detection + per-key bias precompute (log2 domain)
    detect_mask_kernel<<<1, 256>>>((const unsigned char*)mask);
    bias_kernel<<<(Bb * Ts + 255) / 256, 256>>>(eng, mask);

    // 0b) single fused pack launch
    pack_all_kernel<<<4096, 256>>>(x, qkv_w, out_w, xp, wq, wo);

    // 1) fused QKV projection -> Q A-pack, K B-pack, V frag tiles
    dim3 g1(QKV_N / 128, M_ROWS / 128);
    qkv_gemm_fused<<<g1, 128, GP_SMEM_BYTES>>>(xp, wq, qkv_b, qp, kq, vq);

    // 2) attention: 128 queries / CTA, 32 per warp
    dim3 g2(Ts / 128, Hh, Bb);
    attn_kernel<<<g2, 128, ATTN_SMEM_BYTES>>>(qp, op);

    // 3) output projection
    dim3 g3(Dd / 128, M_ROWS / 128);
    f16_gemm_packed<<<g3, 128, GP_SMEM_BYTES>>>(op, wo, out_b, out, Dd, Dd);
}